// round 7
// baseline (speedup 1.0000x reference)
#include <cuda_runtime.h>
#include <cstdint>
#include <cstddef>

#define B_ 4
#define T_ 2048
#define E_ 1024
#define H_ 16
#define D_ 64

// Scratch. q,k,v: [B*H][T][D] tf32-rounded. att: [B,T,H*D] tf32-rounded.
// g_x/g_w/g_wp: tf32-rounded copies of inputs.
__device__ float g_q[(size_t)B_ * H_ * T_ * D_];
__device__ float g_k[(size_t)B_ * H_ * T_ * D_];
__device__ float g_v[(size_t)B_ * H_ * T_ * D_];
__device__ float g_att[(size_t)B_ * T_ * H_ * D_];
__device__ float g_x[(size_t)B_ * T_ * E_];
__device__ float g_w[(size_t)3 * H_ * E_ * D_];
__device__ float g_wp[(size_t)E_ * E_];

__device__ __forceinline__ uint32_t f2tf(float f) {
    uint32_t r;
    asm("cvt.rna.tf32.f32 %0, %1;" : "=r"(r) : "f"(f));
    return r;
}

__device__ __forceinline__ void mma_tf32(float c[4], const uint32_t a[4], const uint32_t b[2]) {
    asm volatile(
        "mma.sync.aligned.m16n8k8.row.col.f32.tf32.tf32.f32 "
        "{%0,%1,%2,%3}, {%4,%5,%6,%7}, {%8,%9}, {%0,%1,%2,%3};"
        : "+f"(c[0]), "+f"(c[1]), "+f"(c[2]), "+f"(c[3])
        : "r"(a[0]), "r"(a[1]), "r"(a[2]), "r"(a[3]), "r"(b[0]), "r"(b[1]));
}

__device__ __forceinline__ uint32_t smem_u32(const void* p) {
    return (uint32_t)__cvta_generic_to_shared(p);
}
__device__ __forceinline__ void cp16(uint32_t s, const void* g) {
    asm volatile("cp.async.cg.shared.global [%0], [%1], 16;" :: "r"(s), "l"(g));
}
__device__ __forceinline__ void cp_commit() { asm volatile("cp.async.commit_group;"); }
__device__ __forceinline__ void cp_wait2() { asm volatile("cp.async.wait_group 2;"); }

// ---------------------------------------------------------------------------
// Kernel 0: pre-round a tensor to tf32 (float4, exact size).
// ---------------------------------------------------------------------------
__global__ __launch_bounds__(256) void prep_kernel(
    const float4* __restrict__ src, float4* __restrict__ dst, int n4) {
    int i = blockIdx.x * 256 + threadIdx.x;
    if (i < n4) {
        float4 v = src[i];
        float4 o;
        o.x = __uint_as_float(f2tf(v.x));
        o.y = __uint_as_float(f2tf(v.y));
        o.z = __uint_as_float(f2tf(v.z));
        o.w = __uint_as_float(f2tf(v.w));
        dst[i] = o;
    }
}

// ---------------------------------------------------------------------------
// Kernel 1: fused QKV GEMM from pre-rounded g_x/g_w. BM=128,BN=128,BK=32.
// 8 warps 2(M)x4(N), warp tile 64x32. cp.async 3-stage smem pipeline.
// Stage layout (words): sA 128*36 = 4608, sB 32*136 = 4352; stage = 8960.
// ---------------------------------------------------------------------------
#define GEMM_STAGE_W 8960
#define N_STAGES 3

__global__ __launch_bounds__(256, 2) void qkv_mma_kernel() {
    extern __shared__ uint32_t dyn[];

    const int mt = blockIdx.x;          // 0..63
    const int nt = blockIdx.y;          // 0..23
    const int ncol0 = nt * 128;
    const int which = ncol0 >> 10;
    const int h0 = (ncol0 & 1023) >> 6;
    const float* gw = g_w + (size_t)which * H_ * E_ * D_ + (size_t)h0 * E_ * D_;
    const float* gx = g_x + (size_t)mt * 128 * E_;

    const int tid = threadIdx.x;
    const int w = tid >> 5, lane = tid & 31;
    const int wm = w >> 2, wn = w & 3;
    const int m0 = wm * 64, n0 = wn * 32;
    const int lr = lane >> 2, lc = lane & 3;

    float acc[4][4][4] = {};

#define QKV_ISSUE(stg, k0)                                                        \
    {                                                                             \
        uint32_t* sA_ = dyn + (stg) * GEMM_STAGE_W;                               \
        uint32_t* sB_ = sA_ + 4608;                                               \
        _Pragma("unroll")                                                         \
        for (int l = 0; l < 4; l++) {                                             \
            int idx = tid + l * 256;                                              \
            { int r = idx >> 3, f = (idx & 7) * 4;                                \
              cp16(smem_u32(&sA_[r * 36 + f]), gx + (size_t)r * E_ + (k0) + f); } \
            { int r = idx >> 5, c = (idx & 31) * 4;                               \
              cp16(smem_u32(&sB_[r * 136 + c]),                                   \
                   gw + (size_t)(c >> 6) * E_ * D_ + (size_t)((k0) + r) * D_ + (c & 63)); } \
        }                                                                         \
    }

    QKV_ISSUE(0, 0); cp_commit();
    QKV_ISSUE(1, 32); cp_commit();
    QKV_ISSUE(2, 64); cp_commit();

    int stg = 0;
    for (int it = 0; it < 32; it++) {
        cp_wait2();
        __syncthreads();
        const uint32_t* sA = dyn + stg * GEMM_STAGE_W;
        const uint32_t* sB = sA + 4608;
#pragma unroll
        for (int ks = 0; ks < 32; ks += 8) {
            uint32_t a[4][4], b[4][2];
#pragma unroll
            for (int mi = 0; mi < 4; mi++) {
                int r0 = m0 + 16 * mi + lr;
                a[mi][0] = sA[r0 * 36 + ks + lc];
                a[mi][1] = sA[(r0 + 8) * 36 + ks + lc];
                a[mi][2] = sA[r0 * 36 + ks + 4 + lc];
                a[mi][3] = sA[(r0 + 8) * 36 + ks + 4 + lc];
            }
#pragma unroll
            for (int ni = 0; ni < 4; ni++) {
                int cb = n0 + 8 * ni + lr;
                b[ni][0] = sB[(ks + lc) * 136 + cb];
                b[ni][1] = sB[(ks + 4 + lc) * 136 + cb];
            }
#pragma unroll
            for (int mi = 0; mi < 4; mi++)
#pragma unroll
                for (int ni = 0; ni < 4; ni++) mma_tf32(acc[mi][ni], a[mi], b[ni]);
        }
        __syncthreads();
        if (it + N_STAGES < 32) QKV_ISSUE(stg, (it + N_STAGES) * 32);
        cp_commit();
        stg = (stg == N_STAGES - 1) ? 0 : stg + 1;
    }

    float* outsel = (which == 0 ? g_q : (which == 1 ? g_k : g_v));
    const int b_ = (mt * 128) / T_;
    const int trow0 = (mt * 128) % T_;
#pragma unroll
    for (int mi = 0; mi < 4; mi++)
#pragma unroll
        for (int ni = 0; ni < 4; ni++) {
            int col = n0 + 8 * ni + 2 * lc;
            int hh = h0 + (col >> 6), dd = col & 63;
            float* base = outsel + ((size_t)(b_ * H_ + hh) * T_ + trow0) * D_ + dd;
            int row0 = m0 + 16 * mi + lr;
            float2 v0 = { __uint_as_float(f2tf(acc[mi][ni][0])),
                          __uint_as_float(f2tf(acc[mi][ni][1])) };
            float2 v1 = { __uint_as_float(f2tf(acc[mi][ni][2])),
                          __uint_as_float(f2tf(acc[mi][ni][3])) };
            *reinterpret_cast<float2*>(base + (size_t)row0 * D_) = v0;
            *reinterpret_cast<float2*>(base + (size_t)(row0 + 8) * D_) = v1;
        }
}

// ---------------------------------------------------------------------------
// Kernel 2: causal flash attention. Q-tile 128 x kv-tile 64, 8 warps, each
// warp 16 q-rows x 64 kv. Q frags in regs (pre-scaled by scale*log2e);
// softmax in regs; P transposed via quad shuffles. K/V cp.async 3-stage.
// Stage layout (words): sK 64*68 = 4352, sV 64*72 = 4608; stage = 8960.
// ---------------------------------------------------------------------------
__global__ __launch_bounds__(256, 2) void attn_mma_kernel() {
    extern __shared__ uint32_t dyn[];

    const int qi = (int)gridDim.x - 1 - (int)blockIdx.x;  // 15..0, biggest first
    const int bh = blockIdx.y;
    const int tid = threadIdx.x;
    const int w = tid >> 5, lane = tid & 31;
    const int lr = lane >> 2, lc = lane & 3;
    const int r_warp = w * 16;
    const float sc2 = 0.125f * 1.44269504f;  // scale * log2(e)

    const float* Qb = g_q + ((size_t)bh * T_ + (size_t)qi * 128) * D_;
    const float* Kb = g_k + (size_t)bh * T_ * D_;
    const float* Vb = g_v + (size_t)bh * T_ * D_;

#define ATTN_ISSUE(stg, jt)                                                     \
    {                                                                           \
        uint32_t* sK_ = dyn + (stg) * GEMM_STAGE_W;                             \
        uint32_t* sV_ = sK_ + 4352;                                             \
        const float* Kj_ = Kb + (size_t)(jt) * 64 * D_;                         \
        const float* Vj_ = Vb + (size_t)(jt) * 64 * D_;                         \
        _Pragma("unroll")                                                       \
        for (int l = 0; l < 4; l++) {                                           \
            int idx = tid + l * 256;                                            \
            int r = idx >> 4, f = (idx & 15) * 4;                               \
            cp16(smem_u32(&sK_[r * 68 + f]), Kj_ + (size_t)r * D_ + f);         \
            cp16(smem_u32(&sV_[r * 72 + f]), Vj_ + (size_t)r * D_ + f);         \
        }                                                                       \
    }

    // Q fragments from gmem (pre-rounded tf32), pre-scaled by scale*log2e.
    uint32_t qa[8][4];
#pragma unroll
    for (int kk = 0; kk < 8; kk++) {
        const float* q0 = Qb + (size_t)(r_warp + lr) * D_ + 8 * kk;
        const float* q1 = Qb + (size_t)(r_warp + lr + 8) * D_ + 8 * kk;
        qa[kk][0] = f2tf(q0[lc] * sc2);
        qa[kk][1] = f2tf(q1[lc] * sc2);
        qa[kk][2] = f2tf(q0[lc + 4] * sc2);
        qa[kk][3] = f2tf(q1[lc + 4] * sc2);
    }

    float m0r = -1e30f, m1r = -1e30f, l0 = 0.f, l1 = 0.f;
    float o[8][4] = {};

    const int jmax = 2 * qi + 1;   // >= 1 always
    ATTN_ISSUE(0, 0); cp_commit();
    ATTN_ISSUE(1, 1); cp_commit();
    if (2 <= jmax) ATTN_ISSUE(2, 2);
    cp_commit();

    int stg = 0;
    for (int j = 0; j <= jmax; j++) {
        cp_wait2();
        __syncthreads();
        const uint32_t* sK = dyn + stg * GEMM_STAGE_W;
        const uint32_t* sV = sK + 4352;

        // S = (sc2*Q) K^T : 16 x 64 per warp
        float s[8][4] = {};
#pragma unroll
        for (int kk = 0; kk < 8; kk++) {
#pragma unroll
            for (int ni = 0; ni < 8; ni++) {
                uint32_t b[2];
                int kr = 8 * ni + lr;
                b[0] = sK[kr * 68 + 8 * kk + lc];
                b[1] = sK[kr * 68 + 8 * kk + 4 + lc];
                mma_tf32(s[ni], qa[kk], b);
            }
        }

        // causal mask (scores already in base-2 domain)
        const int rg0 = qi * 128 + r_warp + lr;
        const int rg1 = rg0 + 8;
        if (j * 64 + 63 > qi * 128 + r_warp) {
#pragma unroll
            for (int ni = 0; ni < 8; ni++) {
                int c0 = j * 64 + 8 * ni + 2 * lc;
                if (c0 > rg0) s[ni][0] = -1e30f;
                if (c0 + 1 > rg0) s[ni][1] = -1e30f;
                if (c0 > rg1) s[ni][2] = -1e30f;
                if (c0 + 1 > rg1) s[ni][3] = -1e30f;
            }
        }

        // register softmax (rows lr and lr+8; quad reduce)
        float mx0 = -1e30f, mx1 = -1e30f;
#pragma unroll
        for (int ni = 0; ni < 8; ni++) {
            mx0 = fmaxf(mx0, fmaxf(s[ni][0], s[ni][1]));
            mx1 = fmaxf(mx1, fmaxf(s[ni][2], s[ni][3]));
        }
        mx0 = fmaxf(mx0, __shfl_xor_sync(0xffffffffu, mx0, 1));
        mx0 = fmaxf(mx0, __shfl_xor_sync(0xffffffffu, mx0, 2));
        mx1 = fmaxf(mx1, __shfl_xor_sync(0xffffffffu, mx1, 1));
        mx1 = fmaxf(mx1, __shfl_xor_sync(0xffffffffu, mx1, 2));
        float mn0 = fmaxf(m0r, mx0), mn1 = fmaxf(m1r, mx1);
        float al0 = exp2f(m0r - mn0), al1 = exp2f(m1r - mn1);
        m0r = mn0; m1r = mn1;
        float ps0 = 0.f, ps1 = 0.f;
#pragma unroll
        for (int ni = 0; ni < 8; ni++) {
            float p0 = __uint_as_float(f2tf(exp2f(s[ni][0] - mn0)));
            float p1 = __uint_as_float(f2tf(exp2f(s[ni][1] - mn0)));
            float p2 = __uint_as_float(f2tf(exp2f(s[ni][2] - mn1)));
            float p3 = __uint_as_float(f2tf(exp2f(s[ni][3] - mn1)));
            s[ni][0] = p0; s[ni][1] = p1; s[ni][2] = p2; s[ni][3] = p3;
            ps0 += p0 + p1; ps1 += p2 + p3;
        }
        ps0 += __shfl_xor_sync(0xffffffffu, ps0, 1);
        ps0 += __shfl_xor_sync(0xffffffffu, ps0, 2);
        ps1 += __shfl_xor_sync(0xffffffffu, ps1, 1);
        ps1 += __shfl_xor_sync(0xffffffffu, ps1, 2);
        l0 = l0 * al0 + ps0;
        l1 = l1 * al1 + ps1;

#pragma unroll
        for (int ni = 0; ni < 8; ni++) {
            o[ni][0] *= al0; o[ni][1] *= al0; o[ni][2] *= al1; o[ni][3] *= al1;
        }

        // P @ V : transpose P (C-layout) -> A-frags via quad shuffles
        const int srcA = (lane & ~3) | (lc >> 1);
        const int srcB = srcA + 2;
#pragma unroll
        for (int kk = 0; kk < 8; kk++) {
            float v0a = __shfl_sync(0xffffffffu, s[kk][0], srcA);
            float v1a = __shfl_sync(0xffffffffu, s[kk][1], srcA);
            float v2a = __shfl_sync(0xffffffffu, s[kk][2], srcA);
            float v3a = __shfl_sync(0xffffffffu, s[kk][3], srcA);
            float v0b = __shfl_sync(0xffffffffu, s[kk][0], srcB);
            float v1b = __shfl_sync(0xffffffffu, s[kk][1], srcB);
            float v2b = __shfl_sync(0xffffffffu, s[kk][2], srcB);
            float v3b = __shfl_sync(0xffffffffu, s[kk][3], srcB);
            uint32_t a[4];
            a[0] = __float_as_uint((lc & 1) ? v1a : v0a);
            a[1] = __float_as_uint((lc & 1) ? v3a : v2a);
            a[2] = __float_as_uint((lc & 1) ? v1b : v0b);
            a[3] = __float_as_uint((lc & 1) ? v3b : v2b);
#pragma unroll
            for (int ni = 0; ni < 8; ni++) {
                uint32_t b[2];
                b[0] = sV[(8 * kk + lc) * 72 + 8 * ni + lr];
                b[1] = sV[(8 * kk + 4 + lc) * 72 + 8 * ni + lr];
                mma_tf32(o[ni], a, b);
            }
        }
        __syncthreads();
        if (j + N_STAGES <= jmax) ATTN_ISSUE(stg, j + N_STAGES);
        cp_commit();
        stg = (stg == N_STAGES - 1) ? 0 : stg + 1;
    }

    // epilogue: att layout [B, T, H*D], pre-rounded to tf32
    const float il0 = 1.f / l0, il1 = 1.f / l1;
    const int b_ = bh >> 4, h = bh & 15;
    float* Ob = g_att + ((size_t)b_ * T_ + (size_t)qi * 128 + r_warp) * (H_ * D_) + h * D_;
#pragma unroll
    for (int ni = 0; ni < 8; ni++) {
        int c = 8 * ni + 2 * lc;
        float2 v0 = { __uint_as_float(f2tf(o[ni][0] * il0)),
                      __uint_as_float(f2tf(o[ni][1] * il0)) };
        float2 v1 = { __uint_as_float(f2tf(o[ni][2] * il1)),
                      __uint_as_float(f2tf(o[ni][3] * il1)) };
        *reinterpret_cast<float2*>(&Ob[(size_t)lr * (H_ * D_) + c]) = v0;
        *reinterpret_cast<float2*>(&Ob[(size_t)(lr + 8) * (H_ * D_) + c]) = v1;
    }
}

// ---------------------------------------------------------------------------
// Kernel 3: output projection + bias from pre-rounded g_att/g_wp.
// Same tiling/pipeline as kernel 1. Grid (64, 8).
// ---------------------------------------------------------------------------
__global__ __launch_bounds__(256, 2) void proj_mma_kernel(
    const float* __restrict__ bias,
    float* __restrict__ C) {
    extern __shared__ uint32_t dyn[];

    const int mt = blockIdx.x;   // 0..63
    const int nt = blockIdx.y;   // 0..7
    const int tid = threadIdx.x;
    const int w = tid >> 5, lane = tid & 31;
    const int wm = w >> 2, wn = w & 3;
    const int m0 = wm * 64, n0 = wn * 32;
    const int lr = lane >> 2, lc = lane & 3;

    const float* Ab = g_att + (size_t)mt * 128 * E_;
    const float* Bw = g_wp + (size_t)nt * 128;

    float acc[4][4][4] = {};

#define PROJ_ISSUE(stg, k0)                                                       \
    {                                                                             \
        uint32_t* sA_ = dyn + (stg) * GEMM_STAGE_W;                               \
        uint32_t* sB_ = sA_ + 4608;                                               \
        _Pragma("unroll")                                                         \
        for (int l = 0; l < 4; l++) {                                             \
            int idx = tid + l * 256;                                              \
            { int r = idx >> 3, f = (idx & 7) * 4;                                \
              cp16(smem_u32(&sA_[r * 36 + f]), Ab + (size_t)r * E_ + (k0) + f); } \
            { int r = idx >> 5, c = (idx & 31) * 4;                               \
              cp16(smem_u32(&sB_[r * 136 + c]),                                   \
                   Bw + (size_t)((k0) + r) * E_ + c); }                           \
        }                                                                         \
    }

    PROJ_ISSUE(0, 0); cp_commit();
    PROJ_ISSUE(1, 32); cp_commit();
    PROJ_ISSUE(2, 64); cp_commit();

    int stg = 0;
    for (int it = 0; it < 32; it++) {
        cp_wait2();
        __syncthreads();
        const uint32_t* sA = dyn + stg * GEMM_STAGE_W;
        const uint32_t* sB = sA + 4608;
#pragma unroll
        for (int ks = 0; ks < 32; ks += 8) {
            uint32_t a[4][4], b[4][2];
#pragma unroll
            for (int mi = 0; mi < 4; mi++) {
                int r0 = m0 + 16 * mi + lr;
                a[mi][0] = sA[r0 * 36 + ks + lc];
                a[mi][1] = sA[(r0 + 8) * 36 + ks + lc];
                a[mi][2] = sA[r0 * 36 + ks + 4 + lc];
                a[mi][3] = sA[(r0 + 8) * 36 + ks + 4 + lc];
            }
#pragma unroll
            for (int ni = 0; ni < 4; ni++) {
                int cb = n0 + 8 * ni + lr;
                b[ni][0] = sB[(ks + lc) * 136 + cb];
                b[ni][1] = sB[(ks + 4 + lc) * 136 + cb];
            }
#pragma unroll
            for (int mi = 0; mi < 4; mi++)
#pragma unroll
                for (int ni = 0; ni < 4; ni++) mma_tf32(acc[mi][ni], a[mi], b[ni]);
        }
        __syncthreads();
        if (it + N_STAGES < 32) PROJ_ISSUE(stg, (it + N_STAGES) * 32);
        cp_commit();
        stg = (stg == N_STAGES - 1) ? 0 : stg + 1;
    }

    float* Cb = C + (size_t)mt * 128 * E_ + (size_t)nt * 128;
#pragma unroll
    for (int mi = 0; mi < 4; mi++)
#pragma unroll
        for (int ni = 0; ni < 4; ni++) {
            int col = n0 + 8 * ni + 2 * lc;
            float b0 = bias[nt * 128 + col], b1 = bias[nt * 128 + col + 1];
            int row0 = m0 + 16 * mi + lr;
            float2 v0 = { acc[mi][ni][0] + b0, acc[mi][ni][1] + b1 };
            float2 v1 = { acc[mi][ni][2] + b0, acc[mi][ni][3] + b1 };
            *reinterpret_cast<float2*>(Cb + (size_t)row0 * E_ + col) = v0;
            *reinterpret_cast<float2*>(Cb + (size_t)(row0 + 8) * E_ + col) = v1;
        }
}

// ---------------------------------------------------------------------------
extern "C" void kernel_launch(void* const* d_in, const int* in_sizes, int n_in,
                              void* d_out, int out_size) {
    const float* x     = (const float*)d_in[0];
    const float* Wq    = (const float*)d_in[1];
    const float* Wk    = (const float*)d_in[2];
    const float* Wv    = (const float*)d_in[3];
    const float* Wproj = (const float*)d_in[4];
    const float* bproj = (const float*)d_in[5];
    float* out = (float*)d_out;

    float *dg_x, *dg_w, *dg_wp;
    cudaGetSymbolAddress((void**)&dg_x, g_x);
    cudaGetSymbolAddress((void**)&dg_w, g_w);
    cudaGetSymbolAddress((void**)&dg_wp, g_wp);

    const int nx4 = B_ * T_ * E_ / 4;           // 2097152
    const int nw4 = H_ * E_ * D_ / 4;           // 262144
    const int np4 = E_ * E_ / 4;                // 262144
    prep_kernel<<<(nx4 + 255) / 256, 256>>>((const float4*)x, (float4*)dg_x, nx4);
    prep_kernel<<<(nw4 + 255) / 256, 256>>>((const float4*)Wq, (float4*)dg_w, nw4);
    prep_kernel<<<(nw4 + 255) / 256, 256>>>((const float4*)Wk, (float4*)(dg_w + (size_t)H_ * E_ * D_), nw4);
    prep_kernel<<<(nw4 + 255) / 256, 256>>>((const float4*)Wv, (float4*)(dg_w + (size_t)2 * H_ * E_ * D_), nw4);
    prep_kernel<<<(np4 + 255) / 256, 256>>>((const float4*)Wproj, (float4*)dg_wp, np4);

    const int dyn_smem = N_STAGES * GEMM_STAGE_W * (int)sizeof(uint32_t);  // 107520
    cudaFuncSetAttribute(qkv_mma_kernel, cudaFuncAttributeMaxDynamicSharedMemorySize, dyn_smem);
    cudaFuncSetAttribute(attn_mma_kernel, cudaFuncAttributeMaxDynamicSharedMemorySize, dyn_smem);
    cudaFuncSetAttribute(proj_mma_kernel, cudaFuncAttributeMaxDynamicSharedMemorySize, dyn_smem);

    qkv_mma_kernel<<<dim3(64, 24), 256, dyn_smem>>>();
    attn_mma_kernel<<<dim3(16, 64), 256, dyn_smem>>>();
    proj_mma_kernel<<<dim3(64, 8), 256, dyn_smem>>>(bproj, out);
}

// round 9
// speedup vs baseline: 1.8511x; 1.8511x over previous
#include <cuda_runtime.h>
#include <cuda_fp16.h>
#include <cstdint>
#include <cstddef>

#define B_ 4
#define T_ 2048
#define E_ 1024
#define H_ 16
#define D_ 64

// fp16 operand tensors
__device__ __half g_qh[(size_t)64 * 2048 * 64];   // [bh][t][d]
__device__ __half g_kh[(size_t)64 * 2048 * 64];   // [bh][t][d]
__device__ __half g_vh[(size_t)64 * 2048 * 64];   // [bh][t][d]
__device__ __half g_vt[(size_t)64 * 64 * 2048];   // [bh][d][t]
__device__ __half g_xh[(size_t)8192 * 1024];      // [m][k]
__device__ __half g_wh[(size_t)3072 * 1024];      // [n][k]  n = which*1024 + h*64 + d
__device__ __half g_wph[(size_t)1024 * 1024];     // [n][k]
__device__ __half g_atth[(size_t)8192 * 1024];    // [m][k]

// ---------------------------------------------------------------------------
// helpers
// ---------------------------------------------------------------------------
__device__ __forceinline__ void mma_f16(float c[4], const uint32_t a[4], const uint32_t b[2]) {
    asm volatile(
        "mma.sync.aligned.m16n8k16.row.col.f32.f16.f16.f32 "
        "{%0,%1,%2,%3}, {%4,%5,%6,%7}, {%8,%9}, {%0,%1,%2,%3};"
        : "+f"(c[0]), "+f"(c[1]), "+f"(c[2]), "+f"(c[3])
        : "r"(a[0]), "r"(a[1]), "r"(a[2]), "r"(a[3]), "r"(b[0]), "r"(b[1]));
}
__device__ __forceinline__ uint32_t smem_u32(const void* p) {
    return (uint32_t)__cvta_generic_to_shared(p);
}
__device__ __forceinline__ void cp16(uint32_t s, const void* g) {
    asm volatile("cp.async.cg.shared.global [%0], [%1], 16;" :: "r"(s), "l"(g));
}
__device__ __forceinline__ void cp_commit() { asm volatile("cp.async.commit_group;"); }
__device__ __forceinline__ void cp_wait1() { asm volatile("cp.async.wait_group 1;"); }

__device__ __forceinline__ uint32_t packh2(float x, float y) {
    __half2 h = __floats2half2_rn(x, y);
    return *reinterpret_cast<uint32_t*>(&h);
}
__device__ __forceinline__ float h2f_rn(float x) {
    return __half2float(__float2half_rn(x));
}

// ---------------------------------------------------------------------------
// prep kernels
// ---------------------------------------------------------------------------
__global__ __launch_bounds__(256) void f2h_kernel(
    const float4* __restrict__ src, uint4* __restrict__ dst, int n8) {
    int i = blockIdx.x * 256 + threadIdx.x;
    if (i < n8) {
        float4 v0 = src[2 * i], v1 = src[2 * i + 1];
        uint4 o;
        o.x = packh2(v0.x, v0.y);
        o.y = packh2(v0.z, v0.w);
        o.z = packh2(v1.x, v1.y);
        o.w = packh2(v1.z, v1.w);
        dst[i] = o;
    }
}

// W [h][e=1024][d=64] -> g_wh rows n = which*1024 + h*64 + d, cols k=e (half)
__global__ __launch_bounds__(256) void prep_w_kernel(
    const float* __restrict__ Wq, const float* __restrict__ Wk, const float* __restrict__ Wv) {
    __shared__ float s[32][65];
    int ks = blockIdx.x, h = blockIdx.y, which = blockIdx.z;
    const float* W = (which == 0 ? Wq : (which == 1 ? Wk : Wv)) + (size_t)h * 65536;
    int t = threadIdx.x;
    { int k = t >> 3, dg = (t & 7) * 8;
      const float4* sr = (const float4*)(W + (size_t)(ks * 32 + k) * 64 + dg);
      float4 a = sr[0], b = sr[1];
      s[k][dg + 0] = a.x; s[k][dg + 1] = a.y; s[k][dg + 2] = a.z; s[k][dg + 3] = a.w;
      s[k][dg + 4] = b.x; s[k][dg + 5] = b.y; s[k][dg + 6] = b.z; s[k][dg + 7] = b.w; }
    __syncthreads();
    int d = t >> 2, part = t & 3;
    uint4 o;
    uint32_t* op = (uint32_t*)&o;
#pragma unroll
    for (int i = 0; i < 4; i++)
        op[i] = packh2(s[part * 8 + 2 * i][d], s[part * 8 + 2 * i + 1][d]);
    __half* dr = g_wh + (size_t)(which * 1024 + h * 64 + d) * 1024 + ks * 32 + part * 8;
    *(uint4*)dr = o;
}

// Wp [k=1024][n=1024] -> g_wph rows n, cols k
__global__ __launch_bounds__(256) void prep_wp_kernel(const float* __restrict__ Wp) {
    __shared__ float s[32][65];
    int ks = blockIdx.x, nb = blockIdx.y;
    int t = threadIdx.x;
    { int k = t >> 3, ng = (t & 7) * 8;
      const float4* sr = (const float4*)(Wp + (size_t)(ks * 32 + k) * 1024 + nb * 64 + ng);
      float4 a = sr[0], b = sr[1];
      s[k][ng + 0] = a.x; s[k][ng + 1] = a.y; s[k][ng + 2] = a.z; s[k][ng + 3] = a.w;
      s[k][ng + 4] = b.x; s[k][ng + 5] = b.y; s[k][ng + 6] = b.z; s[k][ng + 7] = b.w; }
    __syncthreads();
    int n = t >> 2, part = t & 3;
    uint4 o;
    uint32_t* op = (uint32_t*)&o;
#pragma unroll
    for (int i = 0; i < 4; i++)
        op[i] = packh2(s[part * 8 + 2 * i][n], s[part * 8 + 2 * i + 1][n]);
    __half* dr = g_wph + (size_t)(nb * 64 + n) * 1024 + ks * 32 + part * 8;
    *(uint4*)dr = o;
}

// V [bh][t][d] -> Vt [bh][d][t], 64x64 tiles
__global__ __launch_bounds__(256) void vtrans_kernel() {
    __shared__ __half s[64][65];
    const int tt = blockIdx.x, bh = blockIdx.y;
    const int tid = threadIdx.x;
    const __half* src = g_vh + ((size_t)bh * 2048 + tt * 64) * 64;
#pragma unroll
    for (int l = 0; l < 2; l++) {
        int u = tid + l * 256;
        int r = u >> 3, c8 = (u & 7) * 8;
        uint4 v = *(const uint4*)(src + (size_t)r * 64 + c8);
        const __half* hp = (const __half*)&v;
#pragma unroll
        for (int i = 0; i < 8; i++) s[r][c8 + i] = hp[i];
    }
    __syncthreads();
    __half* dst = g_vt + (size_t)bh * 64 * 2048 + tt * 64;
#pragma unroll
    for (int l = 0; l < 2; l++) {
        int u = tid + l * 256;
        int d = u >> 3, c8 = (u & 7) * 8;
        uint4 v;
        __half* hp = (__half*)&v;
#pragma unroll
        for (int i = 0; i < 8; i++) hp[i] = s[c8 + i][d];
        *(uint4*)(dst + (size_t)d * 2048 + c8) = v;
    }
}

// ---------------------------------------------------------------------------
// fp16 GEMM core: CTA 128x128, BK=64 halves, 2-stage cp.async.
// smem per stage (words): A 128*36 = 4608, B 128*36 = 4608; stage = 9216.
// 8 warps 2(M)x4(N), warp tile 64x32, mma m16n8k16: 4 chunks x 16 mma / slab.
// ---------------------------------------------------------------------------
#define GEMM_STAGE_W 9216

#define GEMM_ISSUE(stg, k0, abase, bbase)                                          \
    {                                                                              \
        uint32_t A_b = dynb + (stg) * (GEMM_STAGE_W * 4);                          \
        uint32_t B_b = A_b + 4608 * 4;                                             \
        _Pragma("unroll")                                                          \
        for (int l = 0; l < 4; l++) {                                              \
            int u = tid + l * 256;                                                 \
            int r = u >> 3, cb = (u & 7) * 16;                                     \
            cp16(A_b + r * 144 + cb, (abase) + (size_t)r * 1024 + (k0) + (cb >> 1)); \
            cp16(B_b + r * 144 + cb, (bbase) + (size_t)r * 1024 + (k0) + (cb >> 1)); \
        }                                                                          \
    }

#define GEMM_MAINLOOP(abase, bbase)                                                \
    GEMM_ISSUE(0, 0, abase, bbase); cp_commit();                                   \
    GEMM_ISSUE(1, 64, abase, bbase); cp_commit();                                  \
    for (int it = 0; it < 16; it++) {                                              \
        cp_wait1();                                                                \
        __syncthreads();                                                           \
        const uint32_t* sA = dyn + (it & 1) * GEMM_STAGE_W;                        \
        const uint32_t* sB = sA + 4608;                                            \
        _Pragma("unroll")                                                          \
        for (int ch = 0; ch < 4; ch++) {                                           \
            uint32_t a[4][4], b[4][2];                                             \
            _Pragma("unroll")                                                      \
            for (int mi = 0; mi < 4; mi++) {                                       \
                int r0 = m0 + 16 * mi + lr;                                        \
                a[mi][0] = sA[r0 * 36 + ch * 8 + lc];                              \
                a[mi][1] = sA[(r0 + 8) * 36 + ch * 8 + lc];                        \
                a[mi][2] = sA[r0 * 36 + ch * 8 + 4 + lc];                          \
                a[mi][3] = sA[(r0 + 8) * 36 + ch * 8 + 4 + lc];                    \
            }                                                                      \
            _Pragma("unroll")                                                      \
            for (int ni = 0; ni < 4; ni++) {                                       \
                int nr = n0 + 8 * ni + lr;                                         \
                b[ni][0] = sB[nr * 36 + ch * 8 + lc];                              \
                b[ni][1] = sB[nr * 36 + ch * 8 + 4 + lc];                          \
            }                                                                      \
            _Pragma("unroll")                                                      \
            for (int mi = 0; mi < 4; mi++)                                         \
                _Pragma("unroll")                                                  \
                for (int ni = 0; ni < 4; ni++) mma_f16(acc[mi][ni], a[mi], b[ni]); \
        }                                                                          \
        __syncthreads();                                                           \
        if (it + 2 < 16) GEMM_ISSUE(it & 1, (it + 2) * 64, abase, bbase);          \
        cp_commit();                                                               \
    }

// ---------------------------------------------------------------------------
// Kernel 1: fused QKV GEMM. grid (64, 24).
// ---------------------------------------------------------------------------
__global__ __launch_bounds__(256, 2) void qkv_mma_kernel() {
    extern __shared__ uint32_t dyn[];
    const uint32_t dynb = smem_u32(dyn);

    const int mt = blockIdx.x, nt = blockIdx.y;
    const int tid = threadIdx.x;
    const int w = tid >> 5, lane = tid & 31;
    const int wm = w >> 2, wn = w & 3;
    const int m0 = wm * 64, n0 = wn * 32;
    const int lr = lane >> 2, lc = lane & 3;

    const __half* abase = g_xh + (size_t)mt * 128 * 1024;
    const __half* bbase = g_wh + (size_t)nt * 128 * 1024;

    float acc[4][4][4] = {};
    GEMM_MAINLOOP(abase, bbase);

    const int ncol0 = nt * 128;
    const int which = ncol0 >> 10;
    __half* sel = (which == 0 ? g_qh : (which == 1 ? g_kh : g_vh));
    const int b_ = mt >> 4;
    const int trow0 = (mt & 15) * 128;
#pragma unroll
    for (int mi = 0; mi < 4; mi++)
#pragma unroll
        for (int ni = 0; ni < 4; ni++) {
            int col = ncol0 + n0 + 8 * ni + 2 * lc;
            int h = (col & 1023) >> 6, d = col & 63;
            __half* base = sel + ((size_t)(b_ * 16 + h) * 2048 + trow0) * 64 + d;
            int row0 = m0 + 16 * mi + lr;
            *(uint32_t*)(base + (size_t)row0 * 64) = packh2(acc[mi][ni][0], acc[mi][ni][1]);
            *(uint32_t*)(base + (size_t)(row0 + 8) * 64) = packh2(acc[mi][ni][2], acc[mi][ni][3]);
        }
}

// ---------------------------------------------------------------------------
// Kernel 3: output projection + bias. grid (64, 8). Output fp32.
// ---------------------------------------------------------------------------
__global__ __launch_bounds__(256, 2) void proj_mma_kernel(
    const float* __restrict__ bias, float* __restrict__ C) {
    extern __shared__ uint32_t dyn[];
    const uint32_t dynb = smem_u32(dyn);

    const int mt = blockIdx.x, nt = blockIdx.y;
    const int tid = threadIdx.x;
    const int w = tid >> 5, lane = tid & 31;
    const int wm = w >> 2, wn = w & 3;
    const int m0 = wm * 64, n0 = wn * 32;
    const int lr = lane >> 2, lc = lane & 3;

    const __half* abase = g_atth + (size_t)mt * 128 * 1024;
    const __half* bbase = g_wph + (size_t)nt * 128 * 1024;

    float acc[4][4][4] = {};
    GEMM_MAINLOOP(abase, bbase);

    float* Cb = C + (size_t)mt * 128 * 1024 + nt * 128;
#pragma unroll
    for (int mi = 0; mi < 4; mi++)
#pragma unroll
        for (int ni = 0; ni < 4; ni++) {
            int col = n0 + 8 * ni + 2 * lc;
            float b0 = bias[nt * 128 + col], b1 = bias[nt * 128 + col + 1];
            int row0 = m0 + 16 * mi + lr;
            float2 v0 = { acc[mi][ni][0] + b0, acc[mi][ni][1] + b1 };
            float2 v1 = { acc[mi][ni][2] + b0, acc[mi][ni][3] + b1 };
            *reinterpret_cast<float2*>(Cb + (size_t)row0 * 1024 + col) = v0;
            *reinterpret_cast<float2*>(Cb + (size_t)(row0 + 8) * 1024 + col) = v1;
        }
}

// ---------------------------------------------------------------------------
// Kernel 2: causal flash attention, fp16 mma. Q-tile 128 x kv-tile 64.
// 8 warps, each 16 q-rows x 64 kv. Q frags in regs; softmax in regs;
// P -> A-frags by direct half2 packing (no shuffles). K [t][d], V^T [d][t].
// smem per stage (words): sK 64*36 = 2304, sVt 64*36 = 2304; stage = 4608.
// ---------------------------------------------------------------------------
#define ATT_STAGE_W 4608

__global__ __launch_bounds__(256, 2) void attn_mma_kernel() {
    extern __shared__ uint32_t dyn[];
    const uint32_t dynb = smem_u32(dyn);

    const int qi = (int)gridDim.x - 1 - (int)blockIdx.x;
    const int bh = blockIdx.y;
    const int tid = threadIdx.x;
    const int w = tid >> 5, lane = tid & 31;
    const int lr = lane >> 2, lc = lane & 3;
    const int r_warp = w * 16;
    const float sc2 = 0.125f * 1.44269504f;

    const __half* Qb = g_qh + ((size_t)bh * 2048 + qi * 128) * 64;
    const __half* Kb = g_kh + (size_t)bh * 2048 * 64;
    const __half* Vtb = g_vt + (size_t)bh * 64 * 2048;

#define ATTN_ISSUE(stg, jt)                                                       \
    {                                                                             \
        uint32_t K_b = dynb + (stg) * (ATT_STAGE_W * 4);                          \
        uint32_t V_b = K_b + 2304 * 4;                                            \
        const __half* Kj = Kb + (size_t)(jt) * 64 * 64;                           \
        const __half* Vj = Vtb + (size_t)(jt) * 64;                               \
        _Pragma("unroll")                                                         \
        for (int l = 0; l < 2; l++) {                                             \
            int u = tid + l * 256;                                                \
            int r = u >> 3, cb = (u & 7) * 16;                                    \
            cp16(K_b + r * 144 + cb, Kj + (size_t)r * 64 + (cb >> 1));            \
            cp16(V_b + r * 144 + cb, Vj + (size_t)r * 2048 + (cb >> 1));          \
        }                                                                         \
    }

    // Q fragments (A-layout, fp16) straight from gmem
    uint32_t qa[4][4];
#pragma unroll
    for (int ch = 0; ch < 4; ch++) {
        const __half* q0 = Qb + (size_t)(r_warp + lr) * 64 + ch * 16;
        const __half* q1 = Qb + (size_t)(r_warp + lr + 8) * 64 + ch * 16;
        qa[ch][0] = *(const uint32_t*)(q0 + 2 * lc);
        qa[ch][1] = *(const uint32_t*)(q1 + 2 * lc);
        qa[ch][2] = *(const uint32_t*)(q0 + 8 + 2 * lc);
        qa[ch][3] = *(const uint32_t*)(q1 + 8 + 2 * lc);
    }

    float m0r = -1e30f, m1r = -1e30f, l0 = 0.f, l1 = 0.f;
    float o[8][4] = {};

    const int jmax = 2 * qi + 1;
    ATTN_ISSUE(0, 0); cp_commit();
    ATTN_ISSUE(1, 1); cp_commit();

    for (int j = 0; j <= jmax; j++) {
        cp_wait1();
        __syncthreads();
        const uint32_t* sK = dyn + (j & 1) * ATT_STAGE_W;
        const uint32_t* sV = sK + 2304;

        // S = Q K^T : 16 x 64 per warp (4 chunks x 8 ni)
        float s[8][4] = {};
#pragma unroll
        for (int ch = 0; ch < 4; ch++) {
#pragma unroll
            for (int ni = 0; ni < 8; ni++) {
                uint32_t b[2];
                int kr = 8 * ni + lr;
                b[0] = sK[kr * 36 + ch * 8 + lc];
                b[1] = sK[kr * 36 + ch * 8 + 4 + lc];
                mma_f16(s[ni], qa[ch], b);
            }
        }

        // scale (base-2) + causal mask
        const int rg0 = qi * 128 + r_warp + lr;
        const int rg1 = rg0 + 8;
        if (j * 64 + 63 > qi * 128 + r_warp) {
#pragma unroll
            for (int ni = 0; ni < 8; ni++) {
                int c0 = j * 64 + 8 * ni + 2 * lc;
                s[ni][0] = (c0 <= rg0) ? s[ni][0] * sc2 : -1e30f;
                s[ni][1] = (c0 + 1 <= rg0) ? s[ni][1] * sc2 : -1e30f;
                s[ni][2] = (c0 <= rg1) ? s[ni][2] * sc2 : -1e30f;
                s[ni][3] = (c0 + 1 <= rg1) ? s[ni][3] * sc2 : -1e30f;
            }
        } else {
#pragma unroll
            for (int ni = 0; ni < 8; ni++) {
                s[ni][0] *= sc2; s[ni][1] *= sc2; s[ni][2] *= sc2; s[ni][3] *= sc2;
            }
        }

        // register softmax (rows lr and lr+8; quad reduce)
        float mx0 = -1e30f, mx1 = -1e30f;
#pragma unroll
        for (int ni = 0; ni < 8; ni++) {
            mx0 = fmaxf(mx0, fmaxf(s[ni][0], s[ni][1]));
            mx1 = fmaxf(mx1, fmaxf(s[ni][2], s[ni][3]));
        }
        mx0 = fmaxf(mx0, __shfl_xor_sync(0xffffffffu, mx0, 1));
        mx0 = fmaxf(mx0, __shfl_xor_sync(0xffffffffu, mx0, 2));
        mx1 = fmaxf(mx1, __shfl_xor_sync(0xffffffffu, mx1, 1));
        mx1 = fmaxf(mx1, __shfl_xor_sync(0xffffffffu, mx1, 2));
        float mn0 = fmaxf(m0r, mx0), mn1 = fmaxf(m1r, mx1);
        float al0 = exp2f(m0r - mn0), al1 = exp2f(m1r - mn1);
        m0r = mn0; m1r = mn1;
        float ps0 = 0.f, ps1 = 0.f;
#pragma unroll
        for (int ni = 0; ni < 8; ni++) {
            float p0 = h2f_rn(exp2f(s[ni][0] - mn0));
            float p1 = h2f_rn(exp2f(s[ni][1] - mn0));
            float p2 = h2f_rn(exp2f(s[ni][2] - mn1));
            float p3 = h2f_rn(exp2f(s[ni][3] - mn1));
            s[ni][0] = p0; s[ni][1] = p1; s[ni][2] = p2; s[ni][3] = p3;
            ps0 += p0 + p1; ps1 += p2 + p3;
        }
        ps0 += __shfl_xor_sync(0xffffffffu, ps0, 1);
        ps0 += __shfl_xor_sync(0xffffffffu, ps0, 2);
        ps1 += __shfl_xor_sync(0xffffffffu, ps1, 1);
        ps1 += __shfl_xor_sync(0xffffffffu, ps1, 2);
        l0 = l0 * al0 + ps0;
        l1 = l1 * al1 + ps1;

#pragma unroll
        for (int ni = 0; ni < 8; ni++) {
            o[ni][0] *= al0; o[ni][1] *= al0; o[ni][2] *= al1; o[ni][3] *= al1;
        }

        // P @ V : A-frags are C-frags packed pairwise (no shuffles)
#pragma unroll
        for (int kk = 0; kk < 4; kk++) {
            uint32_t pa[4];
            pa[0] = packh2(s[2 * kk][0], s[2 * kk][1]);
            pa[1] = packh2(s[2 * kk][2], s[2 * kk][3]);
            pa[2] = packh2(s[2 * kk + 1][0], s[2 * kk + 1][1]);
            pa[3] = packh2(s[2 * kk + 1][2], s[2 * kk + 1][3]);
#pragma unroll
            for (int ni = 0; ni < 8; ni++) {
                uint32_t b[2];
                int dr = 8 * ni + lr;
                b[0] = sV[dr * 36 + kk * 8 + lc];
                b[1] = sV[dr * 36 + kk * 8 + 4 + lc];
                mma_f16(o[ni], pa, b);
            }
        }
        __syncthreads();
        if (j + 2 <= jmax) ATTN_ISSUE(j & 1, j + 2);
        cp_commit();
    }

    // epilogue: att half [m][1024]
    const float il0 = 1.f / l0, il1 = 1.f / l1;
    const int b_ = bh >> 4, h = bh & 15;
    const size_t row0 = (size_t)(b_ * 2048 + qi * 128 + r_warp + lr);
    __half* Ob = g_atth + row0 * 1024 + h * 64;
#pragma unroll
    for (int ni = 0; ni < 8; ni++) {
        int c = 8 * ni + 2 * lc;
        *(uint32_t*)(Ob + c) = packh2(o[ni][0] * il0, o[ni][1] * il0);
        *(uint32_t*)(Ob + 8 * 1024 + c) = packh2(o[ni][2] * il1, o[ni][3] * il1);
    }
}

// ---------------------------------------------------------------------------
extern "C" void kernel_launch(void* const* d_in, const int* in_sizes, int n_in,
                              void* d_out, int out_size) {
    const float* x     = (const float*)d_in[0];
    const float* Wq    = (const float*)d_in[1];
    const float* Wk    = (const float*)d_in[2];
    const float* Wv    = (const float*)d_in[3];
    const float* Wproj = (const float*)d_in[4];
    const float* bproj = (const float*)d_in[5];
    float* out = (float*)d_out;

    __half* dg_xh;
    cudaGetSymbolAddress((void**)&dg_xh, g_xh);

    // prep
    f2h_kernel<<<4096, 256>>>((const float4*)x, (uint4*)dg_xh, 8192 * 1024 / 8);
    prep_w_kernel<<<dim3(32, 16, 3), 256>>>(Wq, Wk, Wv);
    prep_wp_kernel<<<dim3(32, 16), 256>>>(Wproj);

    const int gemm_smem = 2 * GEMM_STAGE_W * 4;   // 73728
    const int att_smem = 2 * ATT_STAGE_W * 4;     // 36864
    cudaFuncSetAttribute(qkv_mma_kernel, cudaFuncAttributeMaxDynamicSharedMemorySize, gemm_smem);
    cudaFuncSetAttribute(proj_mma_kernel, cudaFuncAttributeMaxDynamicSharedMemorySize, gemm_smem);
    cudaFuncSetAttribute(attn_mma_kernel, cudaFuncAttributeMaxDynamicSharedMemorySize, att_smem);

    qkv_mma_kernel<<<dim3(64, 24), 256, gemm_smem>>>();
    vtrans_kernel<<<dim3(32, 64), 256>>>();
    attn_mma_kernel<<<dim3(16, 64), 256, att_smem>>>();
    proj_mma_kernel<<<dim3(64, 8), 256, gemm_smem>>>(bproj, out);
}

// round 10
// speedup vs baseline: 1.9832x; 1.0713x over previous
#include <cuda_runtime.h>
#include <cuda_fp16.h>
#include <cstdint>
#include <cstddef>

#define B_ 4
#define T_ 2048
#define E_ 1024
#define H_ 16
#define D_ 64

// fp16 operand tensors
__device__ __half g_qh[(size_t)64 * 2048 * 64];   // [bh][t][d]
__device__ __half g_kh[(size_t)64 * 2048 * 64];   // [bh][t][d]
__device__ __half g_vh[(size_t)64 * 2048 * 64];   // [bh][t][d]
__device__ __half g_vt[(size_t)64 * 64 * 2048];   // [bh][d][t]
__device__ __half g_xh[(size_t)8192 * 1024];      // [m][k]
__device__ __half g_wh[(size_t)3072 * 1024];      // [n][k]
__device__ __half g_wph[(size_t)1024 * 1024];     // [n][k]
__device__ __half g_atth[(size_t)8192 * 1024];    // [m][k]

// ---------------------------------------------------------------------------
// helpers
// ---------------------------------------------------------------------------
__device__ __forceinline__ void mma_f16(float c[4], const uint32_t a[4], const uint32_t b[2]) {
    asm volatile(
        "mma.sync.aligned.m16n8k16.row.col.f32.f16.f16.f32 "
        "{%0,%1,%2,%3}, {%4,%5,%6,%7}, {%8,%9}, {%0,%1,%2,%3};"
        : "+f"(c[0]), "+f"(c[1]), "+f"(c[2]), "+f"(c[3])
        : "r"(a[0]), "r"(a[1]), "r"(a[2]), "r"(a[3]), "r"(b[0]), "r"(b[1]));
}
__device__ __forceinline__ uint32_t smem_u32(const void* p) {
    return (uint32_t)__cvta_generic_to_shared(p);
}
__device__ __forceinline__ void cp16(uint32_t s, const void* g) {
    asm volatile("cp.async.cg.shared.global [%0], [%1], 16;" :: "r"(s), "l"(g));
}
__device__ __forceinline__ void cp_commit() { asm volatile("cp.async.commit_group;"); }
__device__ __forceinline__ void cp_wait1() { asm volatile("cp.async.wait_group 1;"); }

#define LDSM4(r0, r1, r2, r3, addr) \
    asm volatile("ldmatrix.sync.aligned.m8n8.x4.shared.b16 {%0,%1,%2,%3}, [%4];" \
                 : "=r"(r0), "=r"(r1), "=r"(r2), "=r"(r3) : "r"(addr))

__device__ __forceinline__ uint32_t packh2(float x, float y) {
    __half2 h = __floats2half2_rn(x, y);
    return *reinterpret_cast<uint32_t*>(&h);
}
__device__ __forceinline__ float h2f_rn(float x) {
    return __half2float(__float2half_rn(x));
}

// ---------------------------------------------------------------------------
// prep kernels
// ---------------------------------------------------------------------------
__global__ __launch_bounds__(256) void f2h_kernel(
    const float4* __restrict__ src, uint4* __restrict__ dst, int n8) {
    int i = blockIdx.x * 256 + threadIdx.x;
    if (i < n8) {
        float4 v0 = src[2 * i], v1 = src[2 * i + 1];
        uint4 o;
        o.x = packh2(v0.x, v0.y);
        o.y = packh2(v0.z, v0.w);
        o.z = packh2(v1.x, v1.y);
        o.w = packh2(v1.z, v1.w);
        dst[i] = o;
    }
}

// W [h][e=1024][d=64] -> g_wh rows n = which*1024 + h*64 + d, cols k=e (half)
__global__ __launch_bounds__(256) void prep_w_kernel(
    const float* __restrict__ Wq, const float* __restrict__ Wk, const float* __restrict__ Wv) {
    __shared__ float s[32][65];
    int ks = blockIdx.x, h = blockIdx.y, which = blockIdx.z;
    const float* W = (which == 0 ? Wq : (which == 1 ? Wk : Wv)) + (size_t)h * 65536;
    int t = threadIdx.x;
    { int k = t >> 3, dg = (t & 7) * 8;
      const float4* sr = (const float4*)(W + (size_t)(ks * 32 + k) * 64 + dg);
      float4 a = sr[0], b = sr[1];
      s[k][dg + 0] = a.x; s[k][dg + 1] = a.y; s[k][dg + 2] = a.z; s[k][dg + 3] = a.w;
      s[k][dg + 4] = b.x; s[k][dg + 5] = b.y; s[k][dg + 6] = b.z; s[k][dg + 7] = b.w; }
    __syncthreads();
    int d = t >> 2, part = t & 3;
    uint4 o;
    uint32_t* op = (uint32_t*)&o;
#pragma unroll
    for (int i = 0; i < 4; i++)
        op[i] = packh2(s[part * 8 + 2 * i][d], s[part * 8 + 2 * i + 1][d]);
    __half* dr = g_wh + (size_t)(which * 1024 + h * 64 + d) * 1024 + ks * 32 + part * 8;
    *(uint4*)dr = o;
}

// Wp [k=1024][n=1024] -> g_wph rows n, cols k
__global__ __launch_bounds__(256) void prep_wp_kernel(const float* __restrict__ Wp) {
    __shared__ float s[32][65];
    int ks = blockIdx.x, nb = blockIdx.y;
    int t = threadIdx.x;
    { int k = t >> 3, ng = (t & 7) * 8;
      const float4* sr = (const float4*)(Wp + (size_t)(ks * 32 + k) * 1024 + nb * 64 + ng);
      float4 a = sr[0], b = sr[1];
      s[k][ng + 0] = a.x; s[k][ng + 1] = a.y; s[k][ng + 2] = a.z; s[k][ng + 3] = a.w;
      s[k][ng + 4] = b.x; s[k][ng + 5] = b.y; s[k][ng + 6] = b.z; s[k][ng + 7] = b.w; }
    __syncthreads();
    int n = t >> 2, part = t & 3;
    uint4 o;
    uint32_t* op = (uint32_t*)&o;
#pragma unroll
    for (int i = 0; i < 4; i++)
        op[i] = packh2(s[part * 8 + 2 * i][n], s[part * 8 + 2 * i + 1][n]);
    __half* dr = g_wph + (size_t)(nb * 64 + n) * 1024 + ks * 32 + part * 8;
    *(uint4*)dr = o;
}

// V [bh][t][d] -> Vt [bh][d][t], 64x64 tiles
__global__ __launch_bounds__(256) void vtrans_kernel() {
    __shared__ __half s[64][65];
    const int tt = blockIdx.x, bh = blockIdx.y;
    const int tid = threadIdx.x;
    const __half* src = g_vh + ((size_t)bh * 2048 + tt * 64) * 64;
#pragma unroll
    for (int l = 0; l < 2; l++) {
        int u = tid + l * 256;
        int r = u >> 3, c8 = (u & 7) * 8;
        uint4 v = *(const uint4*)(src + (size_t)r * 64 + c8);
        const __half* hp = (const __half*)&v;
#pragma unroll
        for (int i = 0; i < 8; i++) s[r][c8 + i] = hp[i];
    }
    __syncthreads();
    __half* dst = g_vt + (size_t)bh * 64 * 2048 + tt * 64;
#pragma unroll
    for (int l = 0; l < 2; l++) {
        int u = tid + l * 256;
        int d = u >> 3, c8 = (u & 7) * 8;
        uint4 v;
        __half* hp = (__half*)&v;
#pragma unroll
        for (int i = 0; i < 8; i++) hp[i] = s[c8 + i][d];
        *(uint4*)(dst + (size_t)d * 2048 + c8) = v;
    }
}

// ---------------------------------------------------------------------------
// fp16 GEMM core: CTA 128x128, BK=64 halves, 2-stage cp.async, LDSM frags.
// smem per stage (words): A 128*36 = 4608, B 128*36 = 4608; stage = 9216.
// 8 warps 2(M)x4(N), warp tile 64x32, mma m16n8k16: 4 chunks x 16 mma / slab.
// ---------------------------------------------------------------------------
#define GEMM_STAGE_W 9216

#define GEMM_ISSUE(stg, k0, abase, bbase)                                          \
    {                                                                              \
        uint32_t A_b = dynb + (stg) * (GEMM_STAGE_W * 4);                          \
        uint32_t B_b = A_b + 4608 * 4;                                             \
        _Pragma("unroll")                                                          \
        for (int l = 0; l < 4; l++) {                                              \
            int u = tid + l * 256;                                                 \
            int r = u >> 3, cb = (u & 7) * 16;                                     \
            cp16(A_b + r * 144 + cb, (abase) + (size_t)r * 1024 + (k0) + (cb >> 1)); \
            cp16(B_b + r * 144 + cb, (bbase) + (size_t)r * 1024 + (k0) + (cb >> 1)); \
        }                                                                          \
    }

// per-thread LDSM address words (lane-dependent), defined in each GEMM kernel:
//   aoffw = (m0 + (lane&15))*36 + ((lane>>4)<<2)
//   boffw = (n0 + (lane&7) + ((lane>>4)&1)*8)*36 + ((lane>>3)&1)*4
#define GEMM_MAINLOOP(abase, bbase)                                                \
    GEMM_ISSUE(0, 0, abase, bbase); cp_commit();                                   \
    GEMM_ISSUE(1, 64, abase, bbase); cp_commit();                                  \
    for (int it = 0; it < 16; it++) {                                              \
        cp_wait1();                                                                \
        __syncthreads();                                                           \
        uint32_t sAb = dynb + (it & 1) * (GEMM_STAGE_W * 4);                       \
        uint32_t sBb = sAb + 4608 * 4;                                             \
        _Pragma("unroll")                                                          \
        for (int ch = 0; ch < 4; ch++) {                                           \
            uint32_t a[4][4], b[4][2];                                             \
            _Pragma("unroll")                                                      \
            for (int mi = 0; mi < 4; mi++)                                         \
                LDSM4(a[mi][0], a[mi][1], a[mi][2], a[mi][3],                      \
                      sAb + (uint32_t)(aoffw + mi * 16 * 36 + ch * 8) * 4);        \
            _Pragma("unroll")                                                      \
            for (int nj = 0; nj < 2; nj++)                                         \
                LDSM4(b[2 * nj][0], b[2 * nj][1], b[2 * nj + 1][0], b[2 * nj + 1][1], \
                      sBb + (uint32_t)(boffw + nj * 16 * 36 + ch * 8) * 4);        \
            _Pragma("unroll")                                                      \
            for (int mi = 0; mi < 4; mi++)                                         \
                _Pragma("unroll")                                                  \
                for (int ni = 0; ni < 4; ni++) mma_f16(acc[mi][ni], a[mi], b[ni]); \
        }                                                                          \
        __syncthreads();                                                           \
        if (it + 2 < 16) GEMM_ISSUE(it & 1, (it + 2) * 64, abase, bbase);          \
        cp_commit();                                                               \
    }

// ---------------------------------------------------------------------------
// Kernel 1: fused QKV GEMM. grid (64, 24).
// ---------------------------------------------------------------------------
__global__ __launch_bounds__(256, 2) void qkv_mma_kernel() {
    extern __shared__ uint32_t dyn[];
    const uint32_t dynb = smem_u32(dyn);

    const int mt = blockIdx.x, nt = blockIdx.y;
    const int tid = threadIdx.x;
    const int w = tid >> 5, lane = tid & 31;
    const int wm = w >> 2, wn = w & 3;
    const int m0 = wm * 64, n0 = wn * 32;
    const int lr = lane >> 2, lc = lane & 3;
    const int aoffw = (m0 + (lane & 15)) * 36 + ((lane >> 4) << 2);
    const int boffw = (n0 + (lane & 7) + ((lane >> 4) & 1) * 8) * 36 + ((lane >> 3) & 1) * 4;

    const __half* abase = g_xh + (size_t)mt * 128 * 1024;
    const __half* bbase = g_wh + (size_t)nt * 128 * 1024;

    float acc[4][4][4] = {};
    GEMM_MAINLOOP(abase, bbase);

    const int ncol0 = nt * 128;
    const int which = ncol0 >> 10;
    __half* sel = (which == 0 ? g_qh : (which == 1 ? g_kh : g_vh));
    const int b_ = mt >> 4;
    const int trow0 = (mt & 15) * 128;
#pragma unroll
    for (int mi = 0; mi < 4; mi++)
#pragma unroll
        for (int ni = 0; ni < 4; ni++) {
            int col = ncol0 + n0 + 8 * ni + 2 * lc;
            int h = (col & 1023) >> 6, d = col & 63;
            __half* base = sel + ((size_t)(b_ * 16 + h) * 2048 + trow0) * 64 + d;
            int row0 = m0 + 16 * mi + lr;
            *(uint32_t*)(base + (size_t)row0 * 64) = packh2(acc[mi][ni][0], acc[mi][ni][1]);
            *(uint32_t*)(base + (size_t)(row0 + 8) * 64) = packh2(acc[mi][ni][2], acc[mi][ni][3]);
        }
}

// ---------------------------------------------------------------------------
// Kernel 3: output projection + bias. grid (64, 8). Output fp32.
// ---------------------------------------------------------------------------
__global__ __launch_bounds__(256, 2) void proj_mma_kernel(
    const float* __restrict__ bias, float* __restrict__ C) {
    extern __shared__ uint32_t dyn[];
    const uint32_t dynb = smem_u32(dyn);

    const int mt = blockIdx.x, nt = blockIdx.y;
    const int tid = threadIdx.x;
    const int w = tid >> 5, lane = tid & 31;
    const int wm = w >> 2, wn = w & 3;
    const int m0 = wm * 64, n0 = wn * 32;
    const int lr = lane >> 2, lc = lane & 3;
    const int aoffw = (m0 + (lane & 15)) * 36 + ((lane >> 4) << 2);
    const int boffw = (n0 + (lane & 7) + ((lane >> 4) & 1) * 8) * 36 + ((lane >> 3) & 1) * 4;

    const __half* abase = g_atth + (size_t)mt * 128 * 1024;
    const __half* bbase = g_wph + (size_t)nt * 128 * 1024;

    float acc[4][4][4] = {};
    GEMM_MAINLOOP(abase, bbase);

    float* Cb = C + (size_t)mt * 128 * 1024 + nt * 128;
#pragma unroll
    for (int mi = 0; mi < 4; mi++)
#pragma unroll
        for (int ni = 0; ni < 4; ni++) {
            int col = n0 + 8 * ni + 2 * lc;
            float b0 = bias[nt * 128 + col], b1 = bias[nt * 128 + col + 1];
            int row0 = m0 + 16 * mi + lr;
            float2 v0 = { acc[mi][ni][0] + b0, acc[mi][ni][1] + b1 };
            float2 v1 = { acc[mi][ni][2] + b0, acc[mi][ni][3] + b1 };
            *reinterpret_cast<float2*>(Cb + (size_t)row0 * 1024 + col) = v0;
            *reinterpret_cast<float2*>(Cb + (size_t)(row0 + 8) * 1024 + col) = v1;
        }
}

// ---------------------------------------------------------------------------
// Kernel 2: causal flash attention, fp16 mma + LDSM. Q-tile 128 x kv-tile 64.
// 8 warps, each 16 q-rows x 64 kv. Q frags in regs; softmax in regs;
// P -> A-frags by direct half2 packing. K [t][d], V^T [d][t].
// smem per stage (words): sK 64*36 = 2304, sVt 64*36 = 2304; stage = 4608.
// ---------------------------------------------------------------------------
#define ATT_STAGE_W 4608

__global__ __launch_bounds__(256, 2) void attn_mma_kernel() {
    extern __shared__ uint32_t dyn[];
    const uint32_t dynb = smem_u32(dyn);

    const int qi = (int)gridDim.x - 1 - (int)blockIdx.x;
    const int bh = blockIdx.y;
    const int tid = threadIdx.x;
    const int w = tid >> 5, lane = tid & 31;
    const int lr = lane >> 2, lc = lane & 3;
    const int r_warp = w * 16;
    const float sc2 = 0.125f * 1.44269504f;
    // LDSM B-pattern offset (row-within-64-tile + k-word part)
    const int koffw = ((lane & 7) + ((lane >> 4) & 1) * 8) * 36 + ((lane >> 3) & 1) * 4;

    const __half* Qb = g_qh + ((size_t)bh * 2048 + qi * 128) * 64;
    const __half* Kb = g_kh + (size_t)bh * 2048 * 64;
    const __half* Vtb = g_vt + (size_t)bh * 64 * 2048;

#define ATTN_ISSUE(stg, jt)                                                       \
    {                                                                             \
        uint32_t K_b = dynb + (stg) * (ATT_STAGE_W * 4);                          \
        uint32_t V_b = K_b + 2304 * 4;                                            \
        const __half* Kj = Kb + (size_t)(jt) * 64 * 64;                           \
        const __half* Vj = Vtb + (size_t)(jt) * 64;                               \
        _Pragma("unroll")                                                         \
        for (int l = 0; l < 2; l++) {                                             \
            int u = tid + l * 256;                                                \
            int r = u >> 3, cb = (u & 7) * 16;                                    \
            cp16(K_b + r * 144 + cb, Kj + (size_t)r * 64 + (cb >> 1));            \
            cp16(V_b + r * 144 + cb, Vj + (size_t)r * 2048 + (cb >> 1));          \
        }                                                                         \
    }

    // Q fragments (A-layout, fp16) straight from gmem
    uint32_t qa[4][4];
#pragma unroll
    for (int ch = 0; ch < 4; ch++) {
        const __half* q0 = Qb + (size_t)(r_warp + lr) * 64 + ch * 16;
        const __half* q1 = Qb + (size_t)(r_warp + lr + 8) * 64 + ch * 16;
        qa[ch][0] = *(const uint32_t*)(q0 + 2 * lc);
        qa[ch][1] = *(const uint32_t*)(q1 + 2 * lc);
        qa[ch][2] = *(const uint32_t*)(q0 + 8 + 2 * lc);
        qa[ch][3] = *(const uint32_t*)(q1 + 8 + 2 * lc);
    }

    float m0r = -1e30f, m1r = -1e30f, l0 = 0.f, l1 = 0.f;
    float o[8][4] = {};

    const int jmax = 2 * qi + 1;
    ATTN_ISSUE(0, 0); cp_commit();
    ATTN_ISSUE(1, 1); cp_commit();

    for (int j = 0; j <= jmax; j++) {
        cp_wait1();
        __syncthreads();
        uint32_t sKb = dynb + (j & 1) * (ATT_STAGE_W * 4);
        uint32_t sVb = sKb + 2304 * 4;

        // S = Q K^T : 16 x 64 per warp (4 chunks x 8 ni), K frags via LDSM
        float s[8][4] = {};
#pragma unroll
        for (int ch = 0; ch < 4; ch++) {
            uint32_t bk[8][2];
#pragma unroll
            for (int nj = 0; nj < 4; nj++)
                LDSM4(bk[2 * nj][0], bk[2 * nj][1], bk[2 * nj + 1][0], bk[2 * nj + 1][1],
                      sKb + (uint32_t)(koffw + nj * 16 * 36 + ch * 8) * 4);
#pragma unroll
            for (int ni = 0; ni < 8; ni++) mma_f16(s[ni], qa[ch], bk[ni]);
        }

        // scale (base-2) + causal mask
        const int rg0 = qi * 128 + r_warp + lr;
        const int rg1 = rg0 + 8;
        if (j * 64 + 63 > qi * 128 + r_warp) {
#pragma unroll
            for (int ni = 0; ni < 8; ni++) {
                int c0 = j * 64 + 8 * ni + 2 * lc;
                s[ni][0] = (c0 <= rg0) ? s[ni][0] * sc2 : -1e30f;
                s[ni][1] = (c0 + 1 <= rg0) ? s[ni][1] * sc2 : -1e30f;
                s[ni][2] = (c0 <= rg1) ? s[ni][2] * sc2 : -1e30f;
                s[ni][3] = (c0 + 1 <= rg1) ? s[ni][3] * sc2 : -1e30f;
            }
        } else {
#pragma unroll
            for (int ni = 0; ni < 8; ni++) {
                s[ni][0] *= sc2; s[ni][1] *= sc2; s[ni][2] *= sc2; s[ni][3] *= sc2;
            }
        }

        // register softmax (rows lr and lr+8; quad reduce)
        float mx0 = -1e30f, mx1 = -1e30f;
#pragma unroll
        for (int ni = 0; ni < 8; ni++) {
            mx0 = fmaxf(mx0, fmaxf(s[ni][0], s[ni][1]));
            mx1 = fmaxf(mx1, fmaxf(s[ni][2], s[ni][3]));
        }
        mx0 = fmaxf(mx0, __shfl_xor_sync(0xffffffffu, mx0, 1));
        mx0 = fmaxf(mx0, __shfl_xor_sync(0xffffffffu, mx0, 2));
        mx1 = fmaxf(mx1, __shfl_xor_sync(0xffffffffu, mx1, 1));
        mx1 = fmaxf(mx1, __shfl_xor_sync(0xffffffffu, mx1, 2));
        float mn0 = fmaxf(m0r, mx0), mn1 = fmaxf(m1r, mx1);
        float al0 = exp2f(m0r - mn0), al1 = exp2f(m1r - mn1);
        m0r = mn0; m1r = mn1;
        float ps0 = 0.f, ps1 = 0.f;
#pragma unroll
        for (int ni = 0; ni < 8; ni++) {
            float p0 = h2f_rn(exp2f(s[ni][0] - mn0));
            float p1 = h2f_rn(exp2f(s[ni][1] - mn0));
            float p2 = h2f_rn(exp2f(s[ni][2] - mn1));
            float p3 = h2f_rn(exp2f(s[ni][3] - mn1));
            s[ni][0] = p0; s[ni][1] = p1; s[ni][2] = p2; s[ni][3] = p3;
            ps0 += p0 + p1; ps1 += p2 + p3;
        }
        ps0 += __shfl_xor_sync(0xffffffffu, ps0, 1);
        ps0 += __shfl_xor_sync(0xffffffffu, ps0, 2);
        ps1 += __shfl_xor_sync(0xffffffffu, ps1, 1);
        ps1 += __shfl_xor_sync(0xffffffffu, ps1, 2);
        l0 = l0 * al0 + ps0;
        l1 = l1 * al1 + ps1;

#pragma unroll
        for (int ni = 0; ni < 8; ni++) {
            o[ni][0] *= al0; o[ni][1] *= al0; o[ni][2] *= al1; o[ni][3] *= al1;
        }

        // P @ V : A-frags from C-frags (pairwise pack); V^T frags via LDSM
#pragma unroll
        for (int kk = 0; kk < 4; kk++) {
            uint32_t pa[4];
            pa[0] = packh2(s[2 * kk][0], s[2 * kk][1]);
            pa[1] = packh2(s[2 * kk][2], s[2 * kk][3]);
            pa[2] = packh2(s[2 * kk + 1][0], s[2 * kk + 1][1]);
            pa[3] = packh2(s[2 * kk + 1][2], s[2 * kk + 1][3]);
            uint32_t bv[8][2];
#pragma unroll
            for (int nj = 0; nj < 4; nj++)
                LDSM4(bv[2 * nj][0], bv[2 * nj][1], bv[2 * nj + 1][0], bv[2 * nj + 1][1],
                      sVb + (uint32_t)(koffw + nj * 16 * 36 + kk * 8) * 4);
#pragma unroll
            for (int ni = 0; ni < 8; ni++) mma_f16(o[ni], pa, bv[ni]);
        }
        __syncthreads();
        if (j + 2 <= jmax) ATTN_ISSUE(j & 1, j + 2);
        cp_commit();
    }

    // epilogue: att half [m][1024]
    const float il0 = 1.f / l0, il1 = 1.f / l1;
    const int b_ = bh >> 4, h = bh & 15;
    const size_t row0 = (size_t)(b_ * 2048 + qi * 128 + r_warp + lr);
    __half* Ob = g_atth + row0 * 1024 + h * 64;
#pragma unroll
    for (int ni = 0; ni < 8; ni++) {
        int c = 8 * ni + 2 * lc;
        *(uint32_t*)(Ob + c) = packh2(o[ni][0] * il0, o[ni][1] * il0);
        *(uint32_t*)(Ob + 8 * 1024 + c) = packh2(o[ni][2] * il1, o[ni][3] * il1);
    }
}

// ---------------------------------------------------------------------------
extern "C" void kernel_launch(void* const* d_in, const int* in_sizes, int n_in,
                              void* d_out, int out_size) {
    const float* x     = (const float*)d_in[0];
    const float* Wq    = (const float*)d_in[1];
    const float* Wk    = (const float*)d_in[2];
    const float* Wv    = (const float*)d_in[3];
    const float* Wproj = (const float*)d_in[4];
    const float* bproj = (const float*)d_in[5];
    float* out = (float*)d_out;

    __half* dg_xh;
    cudaGetSymbolAddress((void**)&dg_xh, g_xh);

    // prep
    f2h_kernel<<<4096, 256>>>((const float4*)x, (uint4*)dg_xh, 8192 * 1024 / 8);
    prep_w_kernel<<<dim3(32, 16, 3), 256>>>(Wq, Wk, Wv);
    prep_wp_kernel<<<dim3(32, 16), 256>>>(Wproj);

    const int gemm_smem = 2 * GEMM_STAGE_W * 4;   // 73728
    const int att_smem = 2 * ATT_STAGE_W * 4;     // 36864
    cudaFuncSetAttribute(qkv_mma_kernel, cudaFuncAttributeMaxDynamicSharedMemorySize, gemm_smem);
    cudaFuncSetAttribute(proj_mma_kernel, cudaFuncAttributeMaxDynamicSharedMemorySize, gemm_smem);
    cudaFuncSetAttribute(attn_mma_kernel, cudaFuncAttributeMaxDynamicSharedMemorySize, att_smem);

    qkv_mma_kernel<<<dim3(64, 24), 256, gemm_smem>>>();
    vtrans_kernel<<<dim3(32, 64), 256>>>();
    attn_mma_kernel<<<dim3(16, 64), 256, att_smem>>>();
    proj_mma_kernel<<<dim3(64, 8), 256, gemm_smem>>>(bproj, out);
}

// round 11
// speedup vs baseline: 2.0446x; 1.0310x over previous
#include <cuda_runtime.h>
#include <cuda_fp16.h>
#include <cstdint>
#include <cstddef>

#define B_ 4
#define T_ 2048
#define E_ 1024
#define H_ 16
#define D_ 64

// fp16 operand tensors
__device__ __half g_qh[(size_t)64 * 2048 * 64];   // [bh][t][d]
__device__ __half g_kh[(size_t)64 * 2048 * 64];   // [bh][t][d]
__device__ __half g_vh[(size_t)64 * 2048 * 64];   // [bh][t][d]
__device__ __half g_vt[(size_t)64 * 64 * 2048];   // [bh][d][t]
__device__ __half g_xh[(size_t)8192 * 1024];      // [m][k]
__device__ __half g_wh[(size_t)3072 * 1024];      // [n][k]
__device__ __half g_wph[(size_t)1024 * 1024];     // [n][k]
__device__ __half g_atth[(size_t)8192 * 1024];    // [m][k]

// ---------------------------------------------------------------------------
// helpers
// ---------------------------------------------------------------------------
__device__ __forceinline__ void mma_f16(float c[4], const uint32_t a[4], const uint32_t b[2]) {
    asm volatile(
        "mma.sync.aligned.m16n8k16.row.col.f32.f16.f16.f32 "
        "{%0,%1,%2,%3}, {%4,%5,%6,%7}, {%8,%9}, {%0,%1,%2,%3};"
        : "+f"(c[0]), "+f"(c[1]), "+f"(c[2]), "+f"(c[3])
        : "r"(a[0]), "r"(a[1]), "r"(a[2]), "r"(a[3]), "r"(b[0]), "r"(b[1]));
}
__device__ __forceinline__ uint32_t smem_u32(const void* p) {
    return (uint32_t)__cvta_generic_to_shared(p);
}
__device__ __forceinline__ void cp16(uint32_t s, const void* g) {
    asm volatile("cp.async.cg.shared.global [%0], [%1], 16;" :: "r"(s), "l"(g));
}
__device__ __forceinline__ void cp_commit() { asm volatile("cp.async.commit_group;"); }
__device__ __forceinline__ void cp_wait1() { asm volatile("cp.async.wait_group 1;"); }

#define LDSM4(r0, r1, r2, r3, addr) \
    asm volatile("ldmatrix.sync.aligned.m8n8.x4.shared.b16 {%0,%1,%2,%3}, [%4];" \
                 : "=r"(r0), "=r"(r1), "=r"(r2), "=r"(r3) : "r"(addr))

__device__ __forceinline__ uint32_t packh2(float x, float y) {
    __half2 h = __floats2half2_rn(x, y);
    return *reinterpret_cast<uint32_t*>(&h);
}
__device__ __forceinline__ float h2f_rn(float x) {
    return __half2float(__float2half_rn(x));
}

// ---------------------------------------------------------------------------
// prep kernels
// ---------------------------------------------------------------------------
__global__ __launch_bounds__(256) void f2h_kernel(
    const float4* __restrict__ src, uint4* __restrict__ dst, int n8) {
    int i = blockIdx.x * 256 + threadIdx.x;
    if (i < n8) {
        float4 v0 = src[2 * i], v1 = src[2 * i + 1];
        uint4 o;
        o.x = packh2(v0.x, v0.y);
        o.y = packh2(v0.z, v0.w);
        o.z = packh2(v1.x, v1.y);
        o.w = packh2(v1.z, v1.w);
        dst[i] = o;
    }
}

// W [h][e=1024][d=64] -> g_wh rows n = which*1024 + h*64 + d, cols k=e (half)
__global__ __launch_bounds__(256) void prep_w_kernel(
    const float* __restrict__ Wq, const float* __restrict__ Wk, const float* __restrict__ Wv) {
    __shared__ float s[32][65];
    int ks = blockIdx.x, h = blockIdx.y, which = blockIdx.z;
    const float* W = (which == 0 ? Wq : (which == 1 ? Wk : Wv)) + (size_t)h * 65536;
    int t = threadIdx.x;
    { int k = t >> 3, dg = (t & 7) * 8;
      const float4* sr = (const float4*)(W + (size_t)(ks * 32 + k) * 64 + dg);
      float4 a = sr[0], b = sr[1];
      s[k][dg + 0] = a.x; s[k][dg + 1] = a.y; s[k][dg + 2] = a.z; s[k][dg + 3] = a.w;
      s[k][dg + 4] = b.x; s[k][dg + 5] = b.y; s[k][dg + 6] = b.z; s[k][dg + 7] = b.w; }
    __syncthreads();
    int d = t >> 2, part = t & 3;
    uint4 o;
    uint32_t* op = (uint32_t*)&o;
#pragma unroll
    for (int i = 0; i < 4; i++)
        op[i] = packh2(s[part * 8 + 2 * i][d], s[part * 8 + 2 * i + 1][d]);
    __half* dr = g_wh + (size_t)(which * 1024 + h * 64 + d) * 1024 + ks * 32 + part * 8;
    *(uint4*)dr = o;
}

// Wp [k=1024][n=1024] -> g_wph rows n, cols k
__global__ __launch_bounds__(256) void prep_wp_kernel(const float* __restrict__ Wp) {
    __shared__ float s[32][65];
    int ks = blockIdx.x, nb = blockIdx.y;
    int t = threadIdx.x;
    { int k = t >> 3, ng = (t & 7) * 8;
      const float4* sr = (const float4*)(Wp + (size_t)(ks * 32 + k) * 1024 + nb * 64 + ng);
      float4 a = sr[0], b = sr[1];
      s[k][ng + 0] = a.x; s[k][ng + 1] = a.y; s[k][ng + 2] = a.z; s[k][ng + 3] = a.w;
      s[k][ng + 4] = b.x; s[k][ng + 5] = b.y; s[k][ng + 6] = b.z; s[k][ng + 7] = b.w; }
    __syncthreads();
    int n = t >> 2, part = t & 3;
    uint4 o;
    uint32_t* op = (uint32_t*)&o;
#pragma unroll
    for (int i = 0; i < 4; i++)
        op[i] = packh2(s[part * 8 + 2 * i][n], s[part * 8 + 2 * i + 1][n]);
    __half* dr = g_wph + (size_t)(nb * 64 + n) * 1024 + ks * 32 + part * 8;
    *(uint4*)dr = o;
}

// V [bh][t][d] -> Vt [bh][d][t], 64x64 tiles
__global__ __launch_bounds__(256) void vtrans_kernel() {
    __shared__ __half s[64][65];
    const int tt = blockIdx.x, bh = blockIdx.y;
    const int tid = threadIdx.x;
    const __half* src = g_vh + ((size_t)bh * 2048 + tt * 64) * 64;
#pragma unroll
    for (int l = 0; l < 2; l++) {
        int u = tid + l * 256;
        int r = u >> 3, c8 = (u & 7) * 8;
        uint4 v = *(const uint4*)(src + (size_t)r * 64 + c8);
        const __half* hp = (const __half*)&v;
#pragma unroll
        for (int i = 0; i < 8; i++) s[r][c8 + i] = hp[i];
    }
    __syncthreads();
    __half* dst = g_vt + (size_t)bh * 64 * 2048 + tt * 64;
#pragma unroll
    for (int l = 0; l < 2; l++) {
        int u = tid + l * 256;
        int d = u >> 3, c8 = (u & 7) * 8;
        uint4 v;
        __half* hp = (__half*)&v;
#pragma unroll
        for (int i = 0; i < 8; i++) hp[i] = s[c8 + i][d];
        *(uint4*)(dst + (size_t)d * 2048 + c8) = v;
    }
}

// ---------------------------------------------------------------------------
// fp16 GEMM core: CTA 128x128, BK=64 halves, 3-buffer cp.async pipeline with
// ONE __syncthreads per iteration. smem per stage (words): A 4608, B 4608.
// 8 warps 2(M)x4(N), warp tile 64x32, LDSM fragment loads.
// ---------------------------------------------------------------------------
#define GEMM_STAGE_W 9216

#define GEMM_ISSUE(stg, k0, abase, bbase)                                          \
    {                                                                              \
        uint32_t A_b = dynb + (stg) * (GEMM_STAGE_W * 4);                          \
        uint32_t B_b = A_b + 4608 * 4;                                             \
        _Pragma("unroll")                                                          \
        for (int l = 0; l < 4; l++) {                                              \
            int u = tid + l * 256;                                                 \
            int r = u >> 3, cb = (u & 7) * 16;                                     \
            cp16(A_b + r * 144 + cb, (abase) + (size_t)r * 1024 + (k0) + (cb >> 1)); \
            cp16(B_b + r * 144 + cb, (bbase) + (size_t)r * 1024 + (k0) + (cb >> 1)); \
        }                                                                          \
    }

// Single-sync 3-buffer loop. Invariants at iter top: groups {it, it+1} pending.
// wait1 -> buffer it%3 ready; sync -> also retires last iter's reads of (it+2)%3;
// then issue slab it+2 into (it+2)%3 and compute it%3.
#define GEMM_MAINLOOP(abase, bbase)                                                \
    GEMM_ISSUE(0, 0, abase, bbase); cp_commit();                                   \
    GEMM_ISSUE(1, 64, abase, bbase); cp_commit();                                  \
    for (int it = 0; it < 16; it++) {                                              \
        cp_wait1();                                                                \
        __syncthreads();                                                           \
        if (it + 2 < 16) {                                                         \
            int st = (it + 2) % 3;                                                 \
            GEMM_ISSUE(st, (it + 2) * 64, abase, bbase);                           \
        }                                                                          \
        cp_commit();                                                               \
        uint32_t sAb = dynb + (uint32_t)(it % 3) * (GEMM_STAGE_W * 4);             \
        uint32_t sBb = sAb + 4608 * 4;                                             \
        _Pragma("unroll")                                                          \
        for (int ch = 0; ch < 4; ch++) {                                           \
            uint32_t a[4][4], b[4][2];                                             \
            _Pragma("unroll")                                                      \
            for (int mi = 0; mi < 4; mi++)                                         \
                LDSM4(a[mi][0], a[mi][1], a[mi][2], a[mi][3],                      \
                      sAb + (uint32_t)(aoffw + mi * 16 * 36 + ch * 8) * 4);        \
            _Pragma("unroll")                                                      \
            for (int nj = 0; nj < 2; nj++)                                         \
                LDSM4(b[2 * nj][0], b[2 * nj][1], b[2 * nj + 1][0], b[2 * nj + 1][1], \
                      sBb + (uint32_t)(boffw + nj * 16 * 36 + ch * 8) * 4);        \
            _Pragma("unroll")                                                      \
            for (int mi = 0; mi < 4; mi++)                                         \
                _Pragma("unroll")                                                  \
                for (int ni = 0; ni < 4; ni++) mma_f16(acc[mi][ni], a[mi], b[ni]); \
        }                                                                          \
    }

// ---------------------------------------------------------------------------
// Kernel 1: fused QKV GEMM. grid (64, 24).
// ---------------------------------------------------------------------------
__global__ __launch_bounds__(256, 2) void qkv_mma_kernel() {
    extern __shared__ uint32_t dyn[];
    const uint32_t dynb = smem_u32(dyn);

    const int mt = blockIdx.x, nt = blockIdx.y;
    const int tid = threadIdx.x;
    const int w = tid >> 5, lane = tid & 31;
    const int wm = w >> 2, wn = w & 3;
    const int m0 = wm * 64, n0 = wn * 32;
    const int lr = lane >> 2, lc = lane & 3;
    const int aoffw = (m0 + (lane & 15)) * 36 + ((lane >> 4) << 2);
    const int boffw = (n0 + (lane & 7) + ((lane >> 4) & 1) * 8) * 36 + ((lane >> 3) & 1) * 4;

    const __half* abase = g_xh + (size_t)mt * 128 * 1024;
    const __half* bbase = g_wh + (size_t)nt * 128 * 1024;

    float acc[4][4][4] = {};
    GEMM_MAINLOOP(abase, bbase);

    const int ncol0 = nt * 128;
    const int which = ncol0 >> 10;
    __half* sel = (which == 0 ? g_qh : (which == 1 ? g_kh : g_vh));
    const int b_ = mt >> 4;
    const int trow0 = (mt & 15) * 128;
#pragma unroll
    for (int mi = 0; mi < 4; mi++)
#pragma unroll
        for (int ni = 0; ni < 4; ni++) {
            int col = ncol0 + n0 + 8 * ni + 2 * lc;
            int h = (col & 1023) >> 6, d = col & 63;
            __half* base = sel + ((size_t)(b_ * 16 + h) * 2048 + trow0) * 64 + d;
            int row0 = m0 + 16 * mi + lr;
            *(uint32_t*)(base + (size_t)row0 * 64) = packh2(acc[mi][ni][0], acc[mi][ni][1]);
            *(uint32_t*)(base + (size_t)(row0 + 8) * 64) = packh2(acc[mi][ni][2], acc[mi][ni][3]);
        }
}

// ---------------------------------------------------------------------------
// Kernel 3: output projection + bias. grid (64, 8). Output fp32.
// ---------------------------------------------------------------------------
__global__ __launch_bounds__(256, 2) void proj_mma_kernel(
    const float* __restrict__ bias, float* __restrict__ C) {
    extern __shared__ uint32_t dyn[];
    const uint32_t dynb = smem_u32(dyn);

    const int mt = blockIdx.x, nt = blockIdx.y;
    const int tid = threadIdx.x;
    const int w = tid >> 5, lane = tid & 31;
    const int wm = w >> 2, wn = w & 3;
    const int m0 = wm * 64, n0 = wn * 32;
    const int lr = lane >> 2, lc = lane & 3;
    const int aoffw = (m0 + (lane & 15)) * 36 + ((lane >> 4) << 2);
    const int boffw = (n0 + (lane & 7) + ((lane >> 4) & 1) * 8) * 36 + ((lane >> 3) & 1) * 4;

    const __half* abase = g_atth + (size_t)mt * 128 * 1024;
    const __half* bbase = g_wph + (size_t)nt * 128 * 1024;

    float acc[4][4][4] = {};
    GEMM_MAINLOOP(abase, bbase);

    float* Cb = C + (size_t)mt * 128 * 1024 + nt * 128;
#pragma unroll
    for (int mi = 0; mi < 4; mi++)
#pragma unroll
        for (int ni = 0; ni < 4; ni++) {
            int col = n0 + 8 * ni + 2 * lc;
            float b0 = bias[nt * 128 + col], b1 = bias[nt * 128 + col + 1];
            int row0 = m0 + 16 * mi + lr;
            float2 v0 = { acc[mi][ni][0] + b0, acc[mi][ni][1] + b1 };
            float2 v1 = { acc[mi][ni][2] + b0, acc[mi][ni][3] + b1 };
            *reinterpret_cast<float2*>(Cb + (size_t)row0 * 1024 + col) = v0;
            *reinterpret_cast<float2*>(Cb + (size_t)(row0 + 8) * 1024 + col) = v1;
        }
}

// ---------------------------------------------------------------------------
// Kernel 2: causal flash attention, fp16 mma + LDSM. Q-tile 128 x kv-tile 64.
// 3-buffer cp.async pipeline, one sync per kv-tile.
// smem per stage (words): sK 2304, sVt 2304; stage = 4608.
// ---------------------------------------------------------------------------
#define ATT_STAGE_W 4608

__global__ __launch_bounds__(256, 2) void attn_mma_kernel() {
    extern __shared__ uint32_t dyn[];
    const uint32_t dynb = smem_u32(dyn);

    const int qi = (int)gridDim.x - 1 - (int)blockIdx.x;
    const int bh = blockIdx.y;
    const int tid = threadIdx.x;
    const int w = tid >> 5, lane = tid & 31;
    const int lr = lane >> 2, lc = lane & 3;
    const int r_warp = w * 16;
    const float sc2 = 0.125f * 1.44269504f;
    const int koffw = ((lane & 7) + ((lane >> 4) & 1) * 8) * 36 + ((lane >> 3) & 1) * 4;

    const __half* Qb = g_qh + ((size_t)bh * 2048 + qi * 128) * 64;
    const __half* Kb = g_kh + (size_t)bh * 2048 * 64;
    const __half* Vtb = g_vt + (size_t)bh * 64 * 2048;

#define ATTN_ISSUE(stg, jt)                                                       \
    {                                                                             \
        uint32_t K_b = dynb + (stg) * (ATT_STAGE_W * 4);                          \
        uint32_t V_b = K_b + 2304 * 4;                                            \
        const __half* Kj = Kb + (size_t)(jt) * 64 * 64;                           \
        const __half* Vj = Vtb + (size_t)(jt) * 64;                               \
        _Pragma("unroll")                                                         \
        for (int l = 0; l < 2; l++) {                                             \
            int u = tid + l * 256;                                                \
            int r = u >> 3, cb = (u & 7) * 16;                                    \
            cp16(K_b + r * 144 + cb, Kj + (size_t)r * 64 + (cb >> 1));            \
            cp16(V_b + r * 144 + cb, Vj + (size_t)r * 2048 + (cb >> 1));          \
        }                                                                         \
    }

    // Q fragments (A-layout, fp16) straight from gmem
    uint32_t qa[4][4];
#pragma unroll
    for (int ch = 0; ch < 4; ch++) {
        const __half* q0 = Qb + (size_t)(r_warp + lr) * 64 + ch * 16;
        const __half* q1 = Qb + (size_t)(r_warp + lr + 8) * 64 + ch * 16;
        qa[ch][0] = *(const uint32_t*)(q0 + 2 * lc);
        qa[ch][1] = *(const uint32_t*)(q1 + 2 * lc);
        qa[ch][2] = *(const uint32_t*)(q0 + 8 + 2 * lc);
        qa[ch][3] = *(const uint32_t*)(q1 + 8 + 2 * lc);
    }

    float m0r = -1e30f, m1r = -1e30f, l0 = 0.f, l1 = 0.f;
    float o[8][4] = {};

    const int jmax = 2 * qi + 1;
    ATTN_ISSUE(0, 0); cp_commit();
    ATTN_ISSUE(1, 1); cp_commit();

    for (int j = 0; j <= jmax; j++) {
        cp_wait1();
        __syncthreads();
        if (j + 2 <= jmax) {
            int st = (j + 2) % 3;
            ATTN_ISSUE(st, j + 2);
        }
        cp_commit();
        uint32_t sKb = dynb + (uint32_t)(j % 3) * (ATT_STAGE_W * 4);
        uint32_t sVb = sKb + 2304 * 4;

        // S = Q K^T : 16 x 64 per warp (4 chunks x 8 ni), K frags via LDSM
        float s[8][4] = {};
#pragma unroll
        for (int ch = 0; ch < 4; ch++) {
            uint32_t bk[8][2];
#pragma unroll
            for (int nj = 0; nj < 4; nj++)
                LDSM4(bk[2 * nj][0], bk[2 * nj][1], bk[2 * nj + 1][0], bk[2 * nj + 1][1],
                      sKb + (uint32_t)(koffw + nj * 16 * 36 + ch * 8) * 4);
#pragma unroll
            for (int ni = 0; ni < 8; ni++) mma_f16(s[ni], qa[ch], bk[ni]);
        }

        // scale (base-2) + causal mask
        const int rg0 = qi * 128 + r_warp + lr;
        const int rg1 = rg0 + 8;
        if (j * 64 + 63 > qi * 128 + r_warp) {
#pragma unroll
            for (int ni = 0; ni < 8; ni++) {
                int c0 = j * 64 + 8 * ni + 2 * lc;
                s[ni][0] = (c0 <= rg0) ? s[ni][0] * sc2 : -1e30f;
                s[ni][1] = (c0 + 1 <= rg0) ? s[ni][1] * sc2 : -1e30f;
                s[ni][2] = (c0 <= rg1) ? s[ni][2] * sc2 : -1e30f;
                s[ni][3] = (c0 + 1 <= rg1) ? s[ni][3] * sc2 : -1e30f;
            }
        } else {
#pragma unroll
            for (int ni = 0; ni < 8; ni++) {
                s[ni][0] *= sc2; s[ni][1] *= sc2; s[ni][2] *= sc2; s[ni][3] *= sc2;
            }
        }

        // register softmax (rows lr and lr+8; quad reduce)
        float mx0 = -1e30f, mx1 = -1e30f;
#pragma unroll
        for (int ni = 0; ni < 8; ni++) {
            mx0 = fmaxf(mx0, fmaxf(s[ni][0], s[ni][1]));
            mx1 = fmaxf(mx1, fmaxf(s[ni][2], s[ni][3]));
        }
        mx0 = fmaxf(mx0, __shfl_xor_sync(0xffffffffu, mx0, 1));
        mx0 = fmaxf(mx0, __shfl_xor_sync(0xffffffffu, mx0, 2));
        mx1 = fmaxf(mx1, __shfl_xor_sync(0xffffffffu, mx1, 1));
        mx1 = fmaxf(mx1, __shfl_xor_sync(0xffffffffu, mx1, 2));
        float mn0 = fmaxf(m0r, mx0), mn1 = fmaxf(m1r, mx1);
        float al0 = exp2f(m0r - mn0), al1 = exp2f(m1r - mn1);
        m0r = mn0; m1r = mn1;
        float ps0 = 0.f, ps1 = 0.f;
#pragma unroll
        for (int ni = 0; ni < 8; ni++) {
            float p0 = h2f_rn(exp2f(s[ni][0] - mn0));
            float p1 = h2f_rn(exp2f(s[ni][1] - mn0));
            float p2 = h2f_rn(exp2f(s[ni][2] - mn1));
            float p3 = h2f_rn(exp2f(s[ni][3] - mn1));
            s[ni][0] = p0; s[ni][1] = p1; s[ni][2] = p2; s[ni][3] = p3;
            ps0 += p0 + p1; ps1 += p2 + p3;
        }
        ps0 += __shfl_xor_sync(0xffffffffu, ps0, 1);
        ps0 += __shfl_xor_sync(0xffffffffu, ps0, 2);
        ps1 += __shfl_xor_sync(0xffffffffu, ps1, 1);
        ps1 += __shfl_xor_sync(0xffffffffu, ps1, 2);
        l0 = l0 * al0 + ps0;
        l1 = l1 * al1 + ps1;

#pragma unroll
        for (int ni = 0; ni < 8; ni++) {
            o[ni][0] *= al0; o[ni][1] *= al0; o[ni][2] *= al1; o[ni][3] *= al1;
        }

        // P @ V : A-frags from C-frags (pairwise pack); V^T frags via LDSM
#pragma unroll
        for (int kk = 0; kk < 4; kk++) {
            uint32_t pa[4];
            pa[0] = packh2(s[2 * kk][0], s[2 * kk][1]);
            pa[1] = packh2(s[2 * kk][2], s[2 * kk][3]);
            pa[2] = packh2(s[2 * kk + 1][0], s[2 * kk + 1][1]);
            pa[3] = packh2(s[2 * kk + 1][2], s[2 * kk + 1][3]);
            uint32_t bv[8][2];
#pragma unroll
            for (int nj = 0; nj < 4; nj++)
                LDSM4(bv[2 * nj][0], bv[2 * nj][1], bv[2 * nj + 1][0], bv[2 * nj + 1][1],
                      sVb + (uint32_t)(koffw + nj * 16 * 36 + kk * 8) * 4);
#pragma unroll
            for (int ni = 0; ni < 8; ni++) mma_f16(o[ni], pa, bv[ni]);
        }
    }

    // epilogue: att half [m][1024]
    const float il0 = 1.f / l0, il1 = 1.f / l1;
    const int b_ = bh >> 4, h = bh & 15;
    const size_t row0 = (size_t)(b_ * 2048 + qi * 128 + r_warp + lr);
    __half* Ob = g_atth + row0 * 1024 + h * 64;
#pragma unroll
    for (int ni = 0; ni < 8; ni++) {
        int c = 8 * ni + 2 * lc;
        *(uint32_t*)(Ob + c) = packh2(o[ni][0] * il0, o[ni][1] * il0);
        *(uint32_t*)(Ob + 8 * 1024 + c) = packh2(o[ni][2] * il1, o[ni][3] * il1);
    }
}

// ---------------------------------------------------------------------------
extern "C" void kernel_launch(void* const* d_in, const int* in_sizes, int n_in,
                              void* d_out, int out_size) {
    const float* x     = (const float*)d_in[0];
    const float* Wq    = (const float*)d_in[1];
    const float* Wk    = (const float*)d_in[2];
    const float* Wv    = (const float*)d_in[3];
    const float* Wproj = (const float*)d_in[4];
    const float* bproj = (const float*)d_in[5];
    float* out = (float*)d_out;

    __half* dg_xh;
    cudaGetSymbolAddress((void**)&dg_xh, g_xh);

    // prep
    f2h_kernel<<<4096, 256>>>((const float4*)x, (uint4*)dg_xh, 8192 * 1024 / 8);
    prep_w_kernel<<<dim3(32, 16, 3), 256>>>(Wq, Wk, Wv);
    prep_wp_kernel<<<dim3(32, 16), 256>>>(Wproj);

    const int gemm_smem = 3 * GEMM_STAGE_W * 4;   // 110592
    const int att_smem = 3 * ATT_STAGE_W * 4;     // 55296
    cudaFuncSetAttribute(qkv_mma_kernel, cudaFuncAttributeMaxDynamicSharedMemorySize, gemm_smem);
    cudaFuncSetAttribute(proj_mma_kernel, cudaFuncAttributeMaxDynamicSharedMemorySize, gemm_smem);
    cudaFuncSetAttribute(attn_mma_kernel, cudaFuncAttributeMaxDynamicSharedMemorySize, att_smem);

    qkv_mma_kernel<<<dim3(64, 24), 256, gemm_smem>>>();
    vtrans_kernel<<<dim3(32, 64), 256>>>();
    attn_mma_kernel<<<dim3(16, 64), 256, att_smem>>>();
    proj_mma_kernel<<<dim3(64, 8), 256, gemm_smem>>>(bproj, out);
}

// round 13
// speedup vs baseline: 2.0517x; 1.0035x over previous
#include <cuda_runtime.h>
#include <cuda_fp16.h>
#include <cstdint>
#include <cstddef>

#define B_ 4
#define T_ 2048
#define E_ 1024
#define H_ 16
#define D_ 64

// fp16 operand tensors
__device__ __half g_qh[(size_t)64 * 2048 * 64];   // [bh][t][d]
__device__ __half g_kh[(size_t)64 * 2048 * 64];   // [bh][t][d]
__device__ __half g_vh[(size_t)64 * 2048 * 64];   // [bh][t][d]
__device__ __half g_vt[(size_t)64 * 64 * 2048];   // [bh][d][t]
__device__ __half g_xh[(size_t)8192 * 1024];      // [m][k]
__device__ __half g_wh[(size_t)3072 * 1024];      // [n][k]
__device__ __half g_wph[(size_t)1024 * 1024];     // [n][k]
__device__ __half g_atth[(size_t)8192 * 1024];    // [m][k]

// ---------------------------------------------------------------------------
// helpers
// ---------------------------------------------------------------------------
__device__ __forceinline__ void mma_f16(float c[4], const uint32_t a[4], const uint32_t b[2]) {
    asm volatile(
        "mma.sync.aligned.m16n8k16.row.col.f32.f16.f16.f32 "
        "{%0,%1,%2,%3}, {%4,%5,%6,%7}, {%8,%9}, {%0,%1,%2,%3};"
        : "+f"(c[0]), "+f"(c[1]), "+f"(c[2]), "+f"(c[3])
        : "r"(a[0]), "r"(a[1]), "r"(a[2]), "r"(a[3]), "r"(b[0]), "r"(b[1]));
}
__device__ __forceinline__ uint32_t smem_u32(const void* p) {
    return (uint32_t)__cvta_generic_to_shared(p);
}
__device__ __forceinline__ void cp16(uint32_t s, const void* g) {
    asm volatile("cp.async.cg.shared.global [%0], [%1], 16;" :: "r"(s), "l"(g));
}
__device__ __forceinline__ void cp_commit() { asm volatile("cp.async.commit_group;"); }
__device__ __forceinline__ void cp_wait1() { asm volatile("cp.async.wait_group 1;"); }

#define LDSM4(r0, r1, r2, r3, addr) \
    asm volatile("ldmatrix.sync.aligned.m8n8.x4.shared.b16 {%0,%1,%2,%3}, [%4];" \
                 : "=r"(r0), "=r"(r1), "=r"(r2), "=r"(r3) : "r"(addr))

__device__ __forceinline__ uint32_t packh2(float x, float y) {
    __half2 h = __floats2half2_rn(x, y);
    return *reinterpret_cast<uint32_t*>(&h);
}
__device__ __forceinline__ float h2f_rn(float x) {
    return __half2float(__float2half_rn(x));
}

// ---------------------------------------------------------------------------
// prep kernels
// ---------------------------------------------------------------------------
__global__ __launch_bounds__(256) void f2h_kernel(
    const float4* __restrict__ src, uint4* __restrict__ dst, int n8) {
    int i = blockIdx.x * 256 + threadIdx.x;
    if (i < n8) {
        float4 v0 = src[2 * i], v1 = src[2 * i + 1];
        uint4 o;
        o.x = packh2(v0.x, v0.y);
        o.y = packh2(v0.z, v0.w);
        o.z = packh2(v1.x, v1.y);
        o.w = packh2(v1.z, v1.w);
        dst[i] = o;
    }
}

// z = 0..2: Wq/Wk/Wv [h][e][d] -> g_wh rows n = z*1024 + h*64 + d, cols k=e
// z = 3:    Wp [k][n]          -> g_wph rows n = y*64 + n, cols k
__global__ __launch_bounds__(256) void prep_all_kernel(
    const float* __restrict__ Wq, const float* __restrict__ Wk,
    const float* __restrict__ Wv, const float* __restrict__ Wp) {
    __shared__ float s[32][65];
    int ks = blockIdx.x, yb = blockIdx.y, which = blockIdx.z;
    int t = threadIdx.x;
    if (which < 3) {
        const float* W = (which == 0 ? Wq : (which == 1 ? Wk : Wv)) + (size_t)yb * 65536;
        { int k = t >> 3, dg = (t & 7) * 8;
          const float4* sr = (const float4*)(W + (size_t)(ks * 32 + k) * 64 + dg);
          float4 a = sr[0], b = sr[1];
          s[k][dg + 0] = a.x; s[k][dg + 1] = a.y; s[k][dg + 2] = a.z; s[k][dg + 3] = a.w;
          s[k][dg + 4] = b.x; s[k][dg + 5] = b.y; s[k][dg + 6] = b.z; s[k][dg + 7] = b.w; }
        __syncthreads();
        int d = t >> 2, part = t & 3;
        uint4 o;
        uint32_t* op = (uint32_t*)&o;
#pragma unroll
        for (int i = 0; i < 4; i++)
            op[i] = packh2(s[part * 8 + 2 * i][d], s[part * 8 + 2 * i + 1][d]);
        __half* dr = g_wh + (size_t)(which * 1024 + yb * 64 + d) * 1024 + ks * 32 + part * 8;
        *(uint4*)dr = o;
    } else {
        { int k = t >> 3, ng = (t & 7) * 8;
          const float4* sr = (const float4*)(Wp + (size_t)(ks * 32 + k) * 1024 + yb * 64 + ng);
          float4 a = sr[0], b = sr[1];
          s[k][ng + 0] = a.x; s[k][ng + 1] = a.y; s[k][ng + 2] = a.z; s[k][ng + 3] = a.w;
          s[k][ng + 4] = b.x; s[k][ng + 5] = b.y; s[k][ng + 6] = b.z; s[k][ng + 7] = b.w; }
        __syncthreads();
        int n = t >> 2, part = t & 3;
        uint4 o;
        uint32_t* op = (uint32_t*)&o;
#pragma unroll
        for (int i = 0; i < 4; i++)
            op[i] = packh2(s[part * 8 + 2 * i][n], s[part * 8 + 2 * i + 1][n]);
        __half* dr = g_wph + (size_t)(yb * 64 + n) * 1024 + ks * 32 + part * 8;
        *(uint4*)dr = o;
    }
}

// V [bh][t][d] -> Vt [bh][d][t], 64x64 tiles
__global__ __launch_bounds__(256) void vtrans_kernel() {
    __shared__ __half s[64][65];
    const int tt = blockIdx.x, bh = blockIdx.y;
    const int tid = threadIdx.x;
    const __half* src = g_vh + ((size_t)bh * 2048 + tt * 64) * 64;
#pragma unroll
    for (int l = 0; l < 2; l++) {
        int u = tid + l * 256;
        int r = u >> 3, c8 = (u & 7) * 8;
        uint4 v = *(const uint4*)(src + (size_t)r * 64 + c8);
        const __half* hp = (const __half*)&v;
#pragma unroll
        for (int i = 0; i < 8; i++) s[r][c8 + i] = hp[i];
    }
    __syncthreads();
    __half* dst = g_vt + (size_t)bh * 64 * 2048 + tt * 64;
#pragma unroll
    for (int l = 0; l < 2; l++) {
        int u = tid + l * 256;
        int d = u >> 3, c8 = (u & 7) * 8;
        uint4 v;
        __half* hp = (__half*)&v;
#pragma unroll
        for (int i = 0; i < 8; i++) hp[i] = s[c8 + i][d];
        *(uint4*)(dst + (size_t)d * 2048 + c8) = v;
    }
}

// ---------------------------------------------------------------------------
// fp16 GEMM core: CTA 128x128, BK=64 halves, 3-buffer cp.async pipeline with
// ONE __syncthreads per iteration. smem per stage (words): A 4608, B 4608.
// 8 warps 2(M)x4(N), warp tile 64x32, LDSM fragment loads.
// ---------------------------------------------------------------------------
#define GEMM_STAGE_W 9216

#define GEMM_ISSUE(stg, k0, abase, bbase)                                          \
    {                                                                              \
        uint32_t A_b = dynb + (stg) * (GEMM_STAGE_W * 4);                          \
        uint32_t B_b = A_b + 4608 * 4;                                             \
        _Pragma("unroll")                                                          \
        for (int l = 0; l < 4; l++) {                                              \
            int u = tid + l * 256;                                                 \
            int r = u >> 3, cb = (u & 7) * 16;                                     \
            cp16(A_b + r * 144 + cb, (abase) + (size_t)r * 1024 + (k0) + (cb >> 1)); \
            cp16(B_b + r * 144 + cb, (bbase) + (size_t)r * 1024 + (k0) + (cb >> 1)); \
        }                                                                          \
    }

#define GEMM_MAINLOOP(abase, bbase)                                                \
    GEMM_ISSUE(0, 0, abase, bbase); cp_commit();                                   \
    GEMM_ISSUE(1, 64, abase, bbase); cp_commit();                                  \
    for (int it = 0; it < 16; it++) {                                              \
        cp_wait1();                                                                \
        __syncthreads();                                                           \
        if (it + 2 < 16) {                                                         \
            int st = (it + 2) % 3;                                                 \
            GEMM_ISSUE(st, (it + 2) * 64, abase, bbase);                           \
        }                                                                          \
        cp_commit();                                                               \
        uint32_t sAb = dynb + (uint32_t)(it % 3) * (GEMM_STAGE_W * 4);             \
        uint32_t sBb = sAb + 4608 * 4;                                             \
        _Pragma("unroll")                                                          \
        for (int ch = 0; ch < 4; ch++) {                                           \
            uint32_t a[4][4], b[4][2];                                             \
            _Pragma("unroll")                                                      \
            for (int mi = 0; mi < 4; mi++)                                         \
                LDSM4(a[mi][0], a[mi][1], a[mi][2], a[mi][3],                      \
                      sAb + (uint32_t)(aoffw + mi * 16 * 36 + ch * 8) * 4);        \
            _Pragma("unroll")                                                      \
            for (int nj = 0; nj < 2; nj++)                                         \
                LDSM4(b[2 * nj][0], b[2 * nj][1], b[2 * nj + 1][0], b[2 * nj + 1][1], \
                      sBb + (uint32_t)(boffw + nj * 16 * 36 + ch * 8) * 4);        \
            _Pragma("unroll")                                                      \
            for (int mi = 0; mi < 4; mi++)                                         \
                _Pragma("unroll")                                                  \
                for (int ni = 0; ni < 4; ni++) mma_f16(acc[mi][ni], a[mi], b[ni]); \
        }                                                                          \
    }

// ---------------------------------------------------------------------------
// Kernel 1: fused QKV GEMM. grid (64, 24).
// ---------------------------------------------------------------------------
__global__ __launch_bounds__(256, 2) void qkv_mma_kernel() {
    extern __shared__ uint32_t dyn[];
    const uint32_t dynb = smem_u32(dyn);

    const int mt = blockIdx.x, nt = blockIdx.y;
    const int tid = threadIdx.x;
    const int w = tid >> 5, lane = tid & 31;
    const int wm = w >> 2, wn = w & 3;
    const int m0 = wm * 64, n0 = wn * 32;
    const int lr = lane >> 2, lc = lane & 3;
    const int aoffw = (m0 + (lane & 15)) * 36 + ((lane >> 4) << 2);
    const int boffw = (n0 + (lane & 7) + ((lane >> 4) & 1) * 8) * 36 + ((lane >> 3) & 1) * 4;

    const __half* abase = g_xh + (size_t)mt * 128 * 1024;
    const __half* bbase = g_wh + (size_t)nt * 128 * 1024;

    float acc[4][4][4] = {};
    GEMM_MAINLOOP(abase, bbase);

    const int ncol0 = nt * 128;
    const int which = ncol0 >> 10;
    __half* sel = (which == 0 ? g_qh : (which == 1 ? g_kh : g_vh));
    const int b_ = mt >> 4;
    const int trow0 = (mt & 15) * 128;
#pragma unroll
    for (int mi = 0; mi < 4; mi++)
#pragma unroll
        for (int ni = 0; ni < 4; ni++) {
            int col = ncol0 + n0 + 8 * ni + 2 * lc;
            int h = (col & 1023) >> 6, d = col & 63;
            __half* base = sel + ((size_t)(b_ * 16 + h) * 2048 + trow0) * 64 + d;
            int row0 = m0 + 16 * mi + lr;
            *(uint32_t*)(base + (size_t)row0 * 64) = packh2(acc[mi][ni][0], acc[mi][ni][1]);
            *(uint32_t*)(base + (size_t)(row0 + 8) * 64) = packh2(acc[mi][ni][2], acc[mi][ni][3]);
        }
}

// ---------------------------------------------------------------------------
// Kernel 3: output projection + bias. grid (64, 8). Output fp32.
// ---------------------------------------------------------------------------
__global__ __launch_bounds__(256, 2) void proj_mma_kernel(
    const float* __restrict__ bias, float* __restrict__ C) {
    extern __shared__ uint32_t dyn[];
    const uint32_t dynb = smem_u32(dyn);

    const int mt = blockIdx.x, nt = blockIdx.y;
    const int tid = threadIdx.x;
    const int w = tid >> 5, lane = tid & 31;
    const int wm = w >> 2, wn = w & 3;
    const int m0 = wm * 64, n0 = wn * 32;
    const int lr = lane >> 2, lc = lane & 3;
    const int aoffw = (m0 + (lane & 15)) * 36 + ((lane >> 4) << 2);
    const int boffw = (n0 + (lane & 7) + ((lane >> 4) & 1) * 8) * 36 + ((lane >> 3) & 1) * 4;

    const __half* abase = g_atth + (size_t)mt * 128 * 1024;
    const __half* bbase = g_wph + (size_t)nt * 128 * 1024;

    float acc[4][4][4] = {};
    GEMM_MAINLOOP(abase, bbase);

    float* Cb = C + (size_t)mt * 128 * 1024 + nt * 128;
#pragma unroll
    for (int mi = 0; mi < 4; mi++)
#pragma unroll
        for (int ni = 0; ni < 4; ni++) {
            int col = n0 + 8 * ni + 2 * lc;
            float b0 = bias[nt * 128 + col], b1 = bias[nt * 128 + col + 1];
            int row0 = m0 + 16 * mi + lr;
            float2 v0 = { acc[mi][ni][0] + b0, acc[mi][ni][1] + b1 };
            float2 v1 = { acc[mi][ni][2] + b0, acc[mi][ni][3] + b1 };
            *reinterpret_cast<float2*>(Cb + (size_t)row0 * 1024 + col) = v0;
            *reinterpret_cast<float2*>(Cb + (size_t)(row0 + 8) * 1024 + col) = v1;
        }
}

// ---------------------------------------------------------------------------
// Kernel 2: causal flash attention, fp16 mma + LDSM. Q-tile 128.
// TWO kv-tiles (64 each) per pipeline stage / barrier. 3 stages.
// Stage layout in WORDS: [K0 | V0 | K1 | V1], each tile KV_TILE_W = 2304
// (64 rows x 36 words). Sub-tile s: K at stage + s*2*KV_TILE_W, V at K + KV_TILE_W.
// ---------------------------------------------------------------------------
#define KV_TILE_W 2304
#define ATT_STAGE_W (4 * KV_TILE_W)   // 9216 words = 36864 bytes

__global__ __launch_bounds__(256, 2) void attn_mma_kernel() {
    extern __shared__ uint32_t dyn[];
    const uint32_t dynb = smem_u32(dyn);

    const int qi = (int)gridDim.x - 1 - (int)blockIdx.x;
    const int bh = blockIdx.y;
    const int tid = threadIdx.x;
    const int w = tid >> 5, lane = tid & 31;
    const int lr = lane >> 2, lc = lane & 3;
    const int r_warp = w * 16;
    const float sc2 = 0.125f * 1.44269504f;
    const int koffw = ((lane & 7) + ((lane >> 4) & 1) * 8) * 36 + ((lane >> 3) & 1) * 4;

    const __half* Qb = g_qh + ((size_t)bh * 2048 + qi * 128) * 64;
    const __half* Kb = g_kh + (size_t)bh * 2048 * 64;
    const __half* Vtb = g_vt + (size_t)bh * 64 * 2048;

// load ONE 64-kv-tile: K at byte base kb, V^T at kb + KV_TILE_W*4 bytes
#define ATTN_LOAD1(kb, jt)                                                        \
    {                                                                             \
        const __half* Kj = Kb + (size_t)(jt) * 64 * 64;                           \
        const __half* Vj = Vtb + (size_t)(jt) * 64;                               \
        _Pragma("unroll")                                                         \
        for (int l = 0; l < 2; l++) {                                             \
            int u = tid + l * 256;                                                \
            int r = u >> 3, cb = (u & 7) * 16;                                    \
            cp16((kb) + r * 144 + cb, Kj + (size_t)r * 64 + (cb >> 1));           \
            cp16((kb) + KV_TILE_W * 4 + r * 144 + cb, Vj + (size_t)r * 2048 + (cb >> 1)); \
        }                                                                         \
    }
// one stage = two tiles jt0, jt0+1
#define ATTN_ISSUE2(stg, jt0)                                                     \
    {                                                                             \
        uint32_t S_b = dynb + (uint32_t)(stg) * (ATT_STAGE_W * 4);                \
        ATTN_LOAD1(S_b, jt0);                                                     \
        ATTN_LOAD1(S_b + 2 * KV_TILE_W * 4, (jt0) + 1);                           \
    }

    // Q fragments (A-layout, fp16) straight from gmem
    uint32_t qa[4][4];
#pragma unroll
    for (int ch = 0; ch < 4; ch++) {
        const __half* q0 = Qb + (size_t)(r_warp + lr) * 64 + ch * 16;
        const __half* q1 = Qb + (size_t)(r_warp + lr + 8) * 64 + ch * 16;
        qa[ch][0] = *(const uint32_t*)(q0 + 2 * lc);
        qa[ch][1] = *(const uint32_t*)(q1 + 2 * lc);
        qa[ch][2] = *(const uint32_t*)(q0 + 8 + 2 * lc);
        qa[ch][3] = *(const uint32_t*)(q1 + 8 + 2 * lc);
    }

    float m0r = -1e30f, m1r = -1e30f, l0 = 0.f, l1 = 0.f;
    float o[8][4] = {};

    const int niter = qi + 1;   // 2*(qi+1) kv-tiles, 2 per iteration
    ATTN_ISSUE2(0, 0); cp_commit();
    if (1 < niter) ATTN_ISSUE2(1, 2);
    cp_commit();

    for (int it = 0; it < niter; it++) {
        cp_wait1();
        __syncthreads();
        if (it + 2 < niter) ATTN_ISSUE2((it + 2) % 3, 2 * (it + 2));
        cp_commit();

#pragma unroll
        for (int sub = 0; sub < 2; sub++) {
            const int j = 2 * it + sub;
            const uint32_t sKb = dynb + (uint32_t)(it % 3) * (ATT_STAGE_W * 4)
                               + (uint32_t)sub * (2 * KV_TILE_W * 4);
            const uint32_t sVb = sKb + KV_TILE_W * 4;

            // S = Q K^T : 16 x 64 per warp
            float s[8][4] = {};
#pragma unroll
            for (int ch = 0; ch < 4; ch++) {
                uint32_t bk[8][2];
#pragma unroll
                for (int nj = 0; nj < 4; nj++)
                    LDSM4(bk[2 * nj][0], bk[2 * nj][1], bk[2 * nj + 1][0], bk[2 * nj + 1][1],
                          sKb + (uint32_t)(koffw + nj * 16 * 36 + ch * 8) * 4);
#pragma unroll
                for (int ni = 0; ni < 8; ni++) mma_f16(s[ni], qa[ch], bk[ni]);
            }

            // scale (base-2) + causal mask
            const int rg0 = qi * 128 + r_warp + lr;
            const int rg1 = rg0 + 8;
            if (j * 64 + 63 > qi * 128 + r_warp) {
#pragma unroll
                for (int ni = 0; ni < 8; ni++) {
                    int c0 = j * 64 + 8 * ni + 2 * lc;
                    s[ni][0] = (c0 <= rg0) ? s[ni][0] * sc2 : -1e30f;
                    s[ni][1] = (c0 + 1 <= rg0) ? s[ni][1] * sc2 : -1e30f;
                    s[ni][2] = (c0 <= rg1) ? s[ni][2] * sc2 : -1e30f;
                    s[ni][3] = (c0 + 1 <= rg1) ? s[ni][3] * sc2 : -1e30f;
                }
            } else {
#pragma unroll
                for (int ni = 0; ni < 8; ni++) {
                    s[ni][0] *= sc2; s[ni][1] *= sc2; s[ni][2] *= sc2; s[ni][3] *= sc2;
                }
            }

            // register softmax (rows lr and lr+8; quad reduce)
            float mx0 = -1e30f, mx1 = -1e30f;
#pragma unroll
            for (int ni = 0; ni < 8; ni++) {
                mx0 = fmaxf(mx0, fmaxf(s[ni][0], s[ni][1]));
                mx1 = fmaxf(mx1, fmaxf(s[ni][2], s[ni][3]));
            }
            mx0 = fmaxf(mx0, __shfl_xor_sync(0xffffffffu, mx0, 1));
            mx0 = fmaxf(mx0, __shfl_xor_sync(0xffffffffu, mx0, 2));
            mx1 = fmaxf(mx1, __shfl_xor_sync(0xffffffffu, mx1, 1));
            mx1 = fmaxf(mx1, __shfl_xor_sync(0xffffffffu, mx1, 2));
            float mn0 = fmaxf(m0r, mx0), mn1 = fmaxf(m1r, mx1);
            float al0 = exp2f(m0r - mn0), al1 = exp2f(m1r - mn1);
            m0r = mn0; m1r = mn1;
            float ps0 = 0.f, ps1 = 0.f;
#pragma unroll
            for (int ni = 0; ni < 8; ni++) {
                float p0 = h2f_rn(exp2f(s[ni][0] - mn0));
                float p1 = h2f_rn(exp2f(s[ni][1] - mn0));
                float p2 = h2f_rn(exp2f(s[ni][2] - mn1));
                float p3 = h2f_rn(exp2f(s[ni][3] - mn1));
                s[ni][0] = p0; s[ni][1] = p1; s[ni][2] = p2; s[ni][3] = p3;
                ps0 += p0 + p1; ps1 += p2 + p3;
            }
            ps0 += __shfl_xor_sync(0xffffffffu, ps0, 1);
            ps0 += __shfl_xor_sync(0xffffffffu, ps0, 2);
            ps1 += __shfl_xor_sync(0xffffffffu, ps1, 1);
            ps1 += __shfl_xor_sync(0xffffffffu, ps1, 2);
            l0 = l0 * al0 + ps0;
            l1 = l1 * al1 + ps1;

#pragma unroll
            for (int ni = 0; ni < 8; ni++) {
                o[ni][0] *= al0; o[ni][1] *= al0; o[ni][2] *= al1; o[ni][3] *= al1;
            }

            // P @ V : A-frags from C-frags (pairwise pack); V^T frags via LDSM
#pragma unroll
            for (int kk = 0; kk < 4; kk++) {
                uint32_t pa[4];
                pa[0] = packh2(s[2 * kk][0], s[2 * kk][1]);
                pa[1] = packh2(s[2 * kk][2], s[2 * kk][3]);
                pa[2] = packh2(s[2 * kk + 1][0], s[2 * kk + 1][1]);
                pa[3] = packh2(s[2 * kk + 1][2], s[2 * kk + 1][3]);
                uint32_t bv[8][2];
#pragma unroll
                for (int nj = 0; nj < 4; nj++)
                    LDSM4(bv[2 * nj][0], bv[2 * nj][1], bv[2 * nj + 1][0], bv[2 * nj + 1][1],
                          sVb + (uint32_t)(koffw + nj * 16 * 36 + kk * 8) * 4);
#pragma unroll
                for (int ni = 0; ni < 8; ni++) mma_f16(o[ni], pa, bv[ni]);
            }
        }
    }

    // epilogue: att half [m][1024]
    const float il0 = 1.f / l0, il1 = 1.f / l1;
    const int b_ = bh >> 4, h = bh & 15;
    const size_t row0 = (size_t)(b_ * 2048 + qi * 128 + r_warp + lr);
    __half* Ob = g_atth + row0 * 1024 + h * 64;
#pragma unroll
    for (int ni = 0; ni < 8; ni++) {
        int c = 8 * ni + 2 * lc;
        *(uint32_t*)(Ob + c) = packh2(o[ni][0] * il0, o[ni][1] * il0);
        *(uint32_t*)(Ob + 8 * 1024 + c) = packh2(o[ni][2] * il1, o[ni][3] * il1);
    }
}

// ---------------------------------------------------------------------------
extern "C" void kernel_launch(void* const* d_in, const int* in_sizes, int n_in,
                              void* d_out, int out_size) {
    const float* x     = (const float*)d_in[0];
    const float* Wq    = (const float*)d_in[1];
    const float* Wk    = (const float*)d_in[2];
    const float* Wv    = (const float*)d_in[3];
    const float* Wproj = (const float*)d_in[4];
    const float* bproj = (const float*)d_in[5];
    float* out = (float*)d_out;

    __half* dg_xh;
    cudaGetSymbolAddress((void**)&dg_xh, g_xh);

    // prep
    f2h_kernel<<<4096, 256>>>((const float4*)x, (uint4*)dg_xh, 8192 * 1024 / 8);
    prep_all_kernel<<<dim3(32, 16, 4), 256>>>(Wq, Wk, Wv, Wproj);

    const int gemm_smem = 3 * GEMM_STAGE_W * 4;   // 110592
    const int att_smem = 3 * ATT_STAGE_W * 4;     // 110592
    cudaFuncSetAttribute(qkv_mma_kernel, cudaFuncAttributeMaxDynamicSharedMemorySize, gemm_smem);
    cudaFuncSetAttribute(proj_mma_kernel, cudaFuncAttributeMaxDynamicSharedMemorySize, gemm_smem);
    cudaFuncSetAttribute(attn_mma_kernel, cudaFuncAttributeMaxDynamicSharedMemorySize, att_smem);

    qkv_mma_kernel<<<dim3(64, 24), 256, gemm_smem>>>();
    vtrans_kernel<<<dim3(32, 64), 256>>>();
    attn_mma_kernel<<<dim3(16, 64), 256, att_smem>>>();
    proj_mma_kernel<<<dim3(64, 8), 256, gemm_smem>>>(bproj, out);
}